// round 11
// baseline (speedup 1.0000x reference)
#include <cuda_runtime.h>
#include <cuda_bf16.h>
#include <cstdint>
#include <math.h>

// Problem constants
#define B_    8192
#define C_    512
#define F_    8
#define COUP_ 1024
#define NBL_  2
#define D1_   256
#define D2_   256

// ---------------------------------------------------------------------------
// Scratch (device globals — no allocations allowed)
// ---------------------------------------------------------------------------
__device__ float g_X0[B_ * C_];
__device__ float g_X1[B_ * C_];
__device__ float g_Abuf[B_ * C_];
__device__ float g_LD[B_];
__device__ float g_scale[F_ * C_];
__device__ float g_lssum[F_];

__device__ __nv_bfloat16 g_Wph[F_ * C_ * C_],              g_Wpl[F_ * C_ * C_];
__device__ __nv_bfloat16 g_w0h[F_ * COUP_ * D1_],          g_w0l[F_ * COUP_ * D1_];
__device__ __nv_bfloat16 g_whh[F_ * NBL_ * COUP_ * COUP_], g_whl[F_ * NBL_ * COUP_ * COUP_];
__device__ __nv_bfloat16 g_woh[F_ * 2 * D2_ * COUP_],      g_wol[F_ * 2 * D2_ * COUP_];

__device__ __nv_bfloat16 g_XFh[B_ * C_],    g_XFl[B_ * C_];
__device__ __nv_bfloat16 g_XAh[B_ * D1_],   g_XAl[B_ * D1_];
__device__ __nv_bfloat16 g_HAh[B_ * COUP_], g_HAl[B_ * COUP_];
__device__ __nv_bfloat16 g_HBh[B_ * COUP_], g_HBl[B_ * COUP_];

// Scheduler state
__device__ int g_ticket;
__device__ int g_scale_ctr;
__device__ int g_prep_ctr;
__device__ int g_ctr[F_ * 6 * 64];   // [flow][stage 0..4=gemm,5=coupling][rowblock]

// Task layout
#define N_WP (F_ * C_ * C_)
#define N_W0 (F_ * COUP_ * D1_)
#define N_WH (F_ * NBL_ * COUP_ * COUP_)
#define N_WO (F_ * 2 * D2_ * COUP_)
#define N_SPLIT_TOTAL (N_WP + N_W0 + N_WH + N_WO)    // 27262976
#define N_TASK_SCALE 8
#define N_TASK_WS 512
#define CHUNK_WS (N_SPLIT_TOTAL / N_TASK_WS)         // 53248
#define N_TASK_P0 32
#define CHUNK_P0 (B_ * C_ / N_TASK_P0)               // 131072
#define N_PREP (N_TASK_SCALE + N_TASK_WS + N_TASK_P0)  // 552
#define TPF 2112                                     // 256+512+512+512+256+64
#define TOTAL_TICKETS (N_PREP + F_ * TPF)            // 17448

// ---------------------------------------------------------------------------
// Helpers
// ---------------------------------------------------------------------------
__device__ __forceinline__ uint32_t smem_u32(const void* p) {
    uint32_t a;
    asm("{ .reg .u64 t; cvta.to.shared.u64 t, %1; cvt.u32.u64 %0, t; }" : "=r"(a) : "l"(p));
    return a;
}
__device__ __forceinline__ void cpasync16(uint32_t s, const void* g) {
    asm volatile("cp.async.cg.shared.global [%0], [%1], 16;" :: "r"(s), "l"(g) : "memory");
}
__device__ __forceinline__ void cp_commit() { asm volatile("cp.async.commit_group;" ::: "memory"); }
__device__ __forceinline__ void cp_wait0()  { asm volatile("cp.async.wait_group 0;" ::: "memory"); }
__device__ __forceinline__ void cp_wait1()  { asm volatile("cp.async.wait_group 1;" ::: "memory"); }
__device__ __forceinline__ void ldsm4(uint32_t* r, uint32_t addr) {
    asm volatile("ldmatrix.sync.aligned.m8n8.x4.shared.b16 {%0,%1,%2,%3}, [%4];"
                 : "=r"(r[0]), "=r"(r[1]), "=r"(r[2]), "=r"(r[3]) : "r"(addr));
}
__device__ __forceinline__ void mma16816(float* d, const uint32_t* a, const uint32_t* b) {
    asm("mma.sync.aligned.m16n8k16.row.col.f32.bf16.bf16.f32 "
        "{%0,%1,%2,%3}, {%4,%5,%6,%7}, {%8,%9}, {%0,%1,%2,%3};"
        : "+f"(d[0]), "+f"(d[1]), "+f"(d[2]), "+f"(d[3])
        : "r"(a[0]), "r"(a[1]), "r"(a[2]), "r"(a[3]), "r"(b[0]), "r"(b[1]));
}
__device__ __forceinline__ uint32_t pk2(__nv_bfloat16 a, __nv_bfloat16 b) {
    return (uint32_t)__bfloat16_as_ushort(a) | ((uint32_t)__bfloat16_as_ushort(b) << 16);
}
__device__ __forceinline__ int ld_vol(const int* p) { return *(volatile const int*)p; }

#define TILE_BYTES 8192
#define STAGE_BYTES 32768
#define NSTAGE 3
#define SM_BIAS_OFF (NSTAGE * STAGE_BYTES)      // 98304
#define SM_TOTAL (SM_BIAS_OFF + 2048)           // 100352 (bias + scale-reduce scratch)

// ---------------------------------------------------------------------------
// One 128x128 GEMM tile (split-bf16, mma.sync); runtime config.
// Y[m0:,n0:] = act(alpha*(A @ B^T + bias));  A: M x K, B: N x K (row-major)
// ---------------------------------------------------------------------------
__device__ void gemm_tile(const __nv_bfloat16* __restrict__ Ah, const __nv_bfloat16* __restrict__ Al,
                          const __nv_bfloat16* __restrict__ Bh, const __nv_bfloat16* __restrict__ Bl,
                          const float* __restrict__ bias,
                          float* __restrict__ Yf, int ldy,
                          __nv_bfloat16* __restrict__ Oh, __nv_bfloat16* __restrict__ Ol,
                          int ldo, int split_w,
                          int K, float alpha, int relu,
                          int m0, int n0, char* smem) {
    const uint32_t sb = smem_u32(smem);
    const int tid  = threadIdx.x;
    const int lane = tid & 31;
    const int wid  = tid >> 5;
    const int warp_m = wid & 3;
    const int warp_n = wid >> 2;

    float* bias_s = (float*)(smem + SM_BIAS_OFF);
    for (int j = tid; j < 128; j += 256) bias_s[j] = bias ? bias[n0 + j] : 0.0f;

    float acc[2][8][4];
#pragma unroll
    for (int mt = 0; mt < 2; mt++)
#pragma unroll
        for (int nt = 0; nt < 8; nt++)
#pragma unroll
            for (int q = 0; q < 4; q++) acc[mt][nt][q] = 0.0f;

    const int nchunks = K >> 5;

    auto prefetch = [&](int st, int kb) {
        uint32_t base = sb + st * STAGE_BYTES;
#pragma unroll
        for (int i = 0; i < 2; i++) {
            int v = tid + i * 256;
            int r = v >> 2, c = v & 3;
            uint32_t sw = (uint32_t)((c ^ ((r >> 1) & 3)) << 4) + r * 64;
            size_t ga = (size_t)(m0 + r) * K + kb + c * 8;
            size_t gb = (size_t)(n0 + r) * K + kb + c * 8;
            cpasync16(base + sw,                  Ah + ga);
            cpasync16(base + TILE_BYTES + sw,     Al + ga);
            cpasync16(base + 2 * TILE_BYTES + sw, Bh + gb);
            cpasync16(base + 3 * TILE_BYTES + sw, Bl + gb);
        }
        cp_commit();
    };

    auto compute = [&](int st) {
        uint32_t base = sb + st * STAGE_BYTES;
#pragma unroll
        for (int ks = 0; ks < 2; ks++) {
            uint32_t ah[2][4], al_[2][4];
#pragma unroll
            for (int mt = 0; mt < 2; mt++) {
                int gq  = lane >> 3;
                int row = warp_m * 32 + mt * 16 + (lane & 7) + (gq & 1) * 8;
                int ch  = ks * 2 + (gq >> 1);
                uint32_t o = row * 64 + ((ch ^ ((row >> 1) & 3)) << 4);
                ldsm4(ah[mt],  base + o);
                ldsm4(al_[mt], base + TILE_BYTES + o);
            }
            uint32_t bh_[4][4], bl_[4][4];
#pragma unroll
            for (int nt = 0; nt < 4; nt++) {
                int row = warp_n * 64 + nt * 16 + (lane & 7) + ((lane >> 4) & 1) * 8;
                int ch  = ks * 2 + ((lane >> 3) & 1);
                uint32_t o = row * 64 + ((ch ^ ((row >> 1) & 3)) << 4);
                ldsm4(bh_[nt], base + 2 * TILE_BYTES + o);
                ldsm4(bl_[nt], base + 3 * TILE_BYTES + o);
            }
#pragma unroll
            for (int mt = 0; mt < 2; mt++)
#pragma unroll
                for (int nt = 0; nt < 4; nt++)
#pragma unroll
                    for (int hf = 0; hf < 2; hf++)
                        mma16816(acc[mt][nt * 2 + hf], ah[mt], &bh_[nt][hf * 2]);
#pragma unroll
            for (int mt = 0; mt < 2; mt++)
#pragma unroll
                for (int nt = 0; nt < 4; nt++)
#pragma unroll
                    for (int hf = 0; hf < 2; hf++)
                        mma16816(acc[mt][nt * 2 + hf], ah[mt], &bl_[nt][hf * 2]);
#pragma unroll
            for (int mt = 0; mt < 2; mt++)
#pragma unroll
                for (int nt = 0; nt < 4; nt++)
#pragma unroll
                    for (int hf = 0; hf < 2; hf++)
                        mma16816(acc[mt][nt * 2 + hf], al_[mt], &bh_[nt][hf * 2]);
        }
    };

    prefetch(0, 0);
    prefetch(1, 32);
    for (int kc = 0; kc < nchunks; kc++) {
        if (kc + 1 < nchunks) cp_wait1();
        else                  cp_wait0();
        __syncthreads();
        if (kc + 2 < nchunks) prefetch((kc + 2) % 3, (kc + 2) * 32);
        compute(kc % 3);
    }

    // epilogue
    const int qr  = lane >> 2;
    const int qc2 = (lane & 3) * 2;
#pragma unroll
    for (int mt = 0; mt < 2; mt++) {
        int r0 = m0 + warp_m * 32 + mt * 16 + qr;
        int r1 = r0 + 8;
#pragma unroll
        for (int nt = 0; nt < 8; nt++) {
            float* d = acc[mt][nt];
            int col_l = warp_n * 64 + nt * 8 + qc2;
            int col_g = n0 + col_l;
            float bb0 = bias_s[col_l], bb1 = bias_s[col_l + 1];
            float v00 = (d[0] + bb0) * alpha;
            float v01 = (d[1] + bb1) * alpha;
            float v10 = (d[2] + bb0) * alpha;
            float v11 = (d[3] + bb1) * alpha;
            if (relu) {
                v00 = fmaxf(v00, 0.0f); v01 = fmaxf(v01, 0.0f);
                v10 = fmaxf(v10, 0.0f); v11 = fmaxf(v11, 0.0f);
            }
            if (Yf) {
                *(float2*)(Yf + (size_t)r0 * ldy + col_g) = make_float2(v00, v01);
                *(float2*)(Yf + (size_t)r1 * ldy + col_g) = make_float2(v10, v11);
            }
            if (Oh && col_g < split_w) {
                __nv_bfloat16 h00 = __float2bfloat16(v00), h01 = __float2bfloat16(v01);
                __nv_bfloat16 h10 = __float2bfloat16(v10), h11 = __float2bfloat16(v11);
                __nv_bfloat16 l00 = __float2bfloat16(v00 - __bfloat162float(h00));
                __nv_bfloat16 l01 = __float2bfloat16(v01 - __bfloat162float(h01));
                __nv_bfloat16 l10 = __float2bfloat16(v10 - __bfloat162float(h10));
                __nv_bfloat16 l11 = __float2bfloat16(v11 - __bfloat162float(h11));
                *(uint32_t*)(Oh + (size_t)r0 * ldo + col_g) = pk2(h00, h01);
                *(uint32_t*)(Oh + (size_t)r1 * ldo + col_g) = pk2(h10, h11);
                *(uint32_t*)(Ol + (size_t)r0 * ldo + col_g) = pk2(l00, l01);
                *(uint32_t*)(Ol + (size_t)r1 * ldo + col_g) = pk2(l10, l11);
            }
        }
    }
}

// ---------------------------------------------------------------------------
// Coupling for 128 rows [m0, m0+128): update x2, log-det, next-flow XF prep
// ---------------------------------------------------------------------------
__device__ void coupling_rows(int f, int m0, const float* __restrict__ off,
                              float* __restrict__ out) {
    const int tid  = threadIdx.x;
    const int warp = tid >> 5;
    const int lane = tid & 31;
    float* X = (f & 1) ? g_X1 : g_X0;
    const int do_next = (f + 1 < F_);
    const float* sc_n  = g_scale + (size_t)((f + 1) % F_) * C_;
    const float* off_n = off + (size_t)((f + 1) % F_) * C_;
    float* out_final = (f == F_ - 1) ? out : nullptr;

    for (int rr = 0; rr < 16; rr++) {
        int row = m0 + warp + rr * 8;
        const float* arow = g_Abuf + (size_t)row * C_;
        float*       xrow = X + (size_t)row * C_;
        __nv_bfloat16* fh = g_XFh + (size_t)row * C_;
        __nv_bfloat16* fl = g_XFl + (size_t)row * C_;
        float* orow = out_final ? (out_final + (size_t)row * C_) : nullptr;

        float sum = 0.0f;
#pragma unroll
        for (int it = 0; it < 8; it++) {
            int c = lane + it * 32;
            float s  = 2.0f * tanhf(arow[c]);
            float t  = arow[D1_ + c];
            float x2 = xrow[D1_ + c] * expf(s) + t;
            xrow[D1_ + c] = x2;
            sum += s;
            float x1v = xrow[c];
            if (do_next) {
                float v1 = fmaf(x1v, sc_n[c],        off_n[c]);
                float v2 = fmaf(x2,  sc_n[D1_ + c],  off_n[D1_ + c]);
                __nv_bfloat16 h1 = __float2bfloat16(v1);
                __nv_bfloat16 h2 = __float2bfloat16(v2);
                fh[c]       = h1;
                fh[D1_ + c] = h2;
                fl[c]       = __float2bfloat16(v1 - __bfloat162float(h1));
                fl[D1_ + c] = __float2bfloat16(v2 - __bfloat162float(h2));
            }
            if (orow) {
                orow[c]       = x1v;
                orow[D1_ + c] = x2;
            }
        }
#pragma unroll
        for (int o = 16; o > 0; o >>= 1)
            sum += __shfl_down_sync(0xFFFFFFFFu, sum, o);
        if (lane == 0) {
            float prev = (f == 0) ? 0.0f : g_LD[row];
            float ld = prev + sum + g_lssum[f];
            g_LD[row] = ld;
            if (out_final) out_final[(size_t)B_ * C_ + row] = ld;
        }
    }
}

// ---------------------------------------------------------------------------
// Scheduler reset
// ---------------------------------------------------------------------------
__global__ void zero_sched_kernel() {
    int i = blockIdx.x * blockDim.x + threadIdx.x;
    if (i == 0) { g_ticket = 0; g_scale_ctr = 0; g_prep_ctr = 0; }
    if (i < F_ * 6 * 64) g_ctr[i] = 0;
}

// ---------------------------------------------------------------------------
// Persistent dataflow kernel: atomic ticket queue over all tasks,
// per-(stage,rowblock) dependency counters. Deadlock-free: the minimum
// outstanding ticket's deps are complete, so its holder always progresses.
// ---------------------------------------------------------------------------
__global__ __launch_bounds__(256, 2)
void flow_persistent(const float* __restrict__ z0,  const float* __restrict__ Wp,
                     const float* __restrict__ gpar, const float* __restrict__ off,
                     const float* __restrict__ w0,  const float* __restrict__ b0,
                     const float* __restrict__ wh,  const float* __restrict__ bh,
                     const float* __restrict__ wo,  const float* __restrict__ bo,
                     float* __restrict__ out) {
    extern __shared__ char smem[];
    __shared__ int s_t;
    const int tid = threadIdx.x;

    for (;;) {
        if (tid == 0) s_t = atomicAdd(&g_ticket, 1);
        __syncthreads();
        const int t = s_t;
        __syncthreads();
        if (t >= TOTAL_TICKETS) break;

        if (t < N_TASK_SCALE) {
            // scale task for flow f
            int f = t;
            float* red = (float*)(smem + SM_BIAS_OFF);   // 512 floats scratch
            float lg[2];
#pragma unroll
            for (int j = 0; j < 2; j++) {
                int c = tid + j * 256;
                float gv = gpar[f * C_ + c];
                float sc = 0.2f * log1pf(expf(0.5f * gv));
                g_scale[f * C_ + c] = sc;
                lg[j] = logf(sc);
            }
            red[tid] = lg[0] + lg[1];
            __syncthreads();
            for (int s = 128; s > 0; s >>= 1) {
                if (tid < s) red[tid] += red[tid + s];
                __syncthreads();
            }
            if (tid == 0) g_lssum[f] = red[0];
            __syncthreads();
            __threadfence();
            if (tid == 0) { atomicAdd(&g_scale_ctr, 1); atomicAdd(&g_prep_ctr, 1); }
            continue;
        }
        if (t < N_TASK_SCALE + N_TASK_WS) {
            // weight split chunk
            int base = (t - N_TASK_SCALE) * CHUNK_WS;
            for (int i = tid; i < CHUNK_WS; i += 256) {
                int k = base + i;
                const float* src; __nv_bfloat16 *hi, *lo;
                if (k < N_WP) { src = Wp; hi = g_Wph; lo = g_Wpl; }
                else if ((k -= N_WP) < N_W0) { src = w0; hi = g_w0h; lo = g_w0l; }
                else if ((k -= N_W0) < N_WH) { src = wh; hi = g_whh; lo = g_whl; }
                else { k -= N_WH; src = wo; hi = g_woh; lo = g_wol; }
                float v = src[k];
                __nv_bfloat16 h = __float2bfloat16(v);
                hi[k] = h;
                lo[k] = __float2bfloat16(v - __bfloat162float(h));
            }
            __syncthreads();
            __threadfence();
            if (tid == 0) atomicAdd(&g_prep_ctr, 1);
            continue;
        }
        if (t < N_PREP) {
            // prep0 chunk: XF = split(z0*scale0 + off0); waits on scale tasks
            if (tid == 0) {
                while (ld_vol(&g_scale_ctr) < N_TASK_SCALE) __nanosleep(200);
                __threadfence();
            }
            __syncthreads();
            int base = (t - N_TASK_SCALE - N_TASK_WS) * CHUNK_P0;
            for (int i = tid; i < CHUNK_P0; i += 256) {
                int j = base + i;
                int c = j & (C_ - 1);
                float v = fmaf(z0[j], g_scale[c], off[c]);
                __nv_bfloat16 h = __float2bfloat16(v);
                g_XFh[j] = h;
                g_XFl[j] = __float2bfloat16(v - __bfloat162float(h));
            }
            __syncthreads();
            __threadfence();
            if (tid == 0) atomicAdd(&g_prep_ctr, 1);
            continue;
        }

        // ---- flow tasks ----
        int u = t - N_PREP;
        int f = u / TPF;
        int v = u % TPF;
        int* ctrF = g_ctr + f * 6 * 64;
        float* Xcur = (f & 1) ? g_X1 : g_X0;

        if (v < 256) {                                  // G1: XF @ Wp^T, K=512
            int m = v >> 2, n = v & 3;
            if (tid == 0) {
                if (f == 0) { while (ld_vol(&g_prep_ctr) < N_PREP) __nanosleep(200); }
                else { while (ld_vol(g_ctr + (f - 1) * 6 * 64 + 5 * 64 + m) < 1) __nanosleep(200); }
                __threadfence();
            }
            __syncthreads();
            gemm_tile(g_XFh, g_XFl,
                      g_Wph + (size_t)f * C_ * C_, g_Wpl + (size_t)f * C_ * C_,
                      nullptr, Xcur, C_,
                      g_XAh, g_XAl, D1_, D1_,
                      C_, 1.0f, 0, m * 128, n * 128, smem);
            __syncthreads();
            __threadfence();
            if (tid == 0) atomicAdd(ctrF + 0 * 64 + m, 1);
            continue;
        }
        if (v < 768) {                                  // G2: relu(x1 @ w0^T + b0), K=256
            int v2 = v - 256;
            int m = v2 >> 3, n = v2 & 7;
            if (tid == 0) { while (ld_vol(ctrF + 0 * 64 + m) < 4) __nanosleep(200); __threadfence(); }
            __syncthreads();
            gemm_tile(g_XAh, g_XAl,
                      g_w0h + (size_t)f * COUP_ * D1_, g_w0l + (size_t)f * COUP_ * D1_,
                      b0 + (size_t)f * COUP_, nullptr, 0,
                      g_HAh, g_HAl, COUP_, COUP_,
                      D1_, 1.0f, 1, m * 128, n * 128, smem);
            __syncthreads();
            __threadfence();
            if (tid == 0) atomicAdd(ctrF + 1 * 64 + m, 1);
            continue;
        }
        if (v < 1280) {                                 // G3: relu(H @ wh0^T + bh0), K=1024
            int v3 = v - 768;
            int m = v3 >> 3, n = v3 & 7;
            if (tid == 0) { while (ld_vol(ctrF + 1 * 64 + m) < 8) __nanosleep(200); __threadfence(); }
            __syncthreads();
            const __nv_bfloat16* wh0h = g_whh + (size_t)f * NBL_ * COUP_ * COUP_;
            const __nv_bfloat16* wh0l = g_whl + (size_t)f * NBL_ * COUP_ * COUP_;
            gemm_tile(g_HAh, g_HAl, wh0h, wh0l,
                      bh + (size_t)f * NBL_ * COUP_, nullptr, 0,
                      g_HBh, g_HBl, COUP_, COUP_,
                      COUP_, 1.0f, 1, m * 128, n * 128, smem);
            __syncthreads();
            __threadfence();
            if (tid == 0) atomicAdd(ctrF + 2 * 64 + m, 1);
            continue;
        }
        if (v < 1792) {                                 // G4: relu(H' @ wh1^T + bh1), K=1024
            int v4 = v - 1280;
            int m = v4 >> 3, n = v4 & 7;
            if (tid == 0) { while (ld_vol(ctrF + 2 * 64 + m) < 8) __nanosleep(200); __threadfence(); }
            __syncthreads();
            const __nv_bfloat16* wh1h = g_whh + (size_t)f * NBL_ * COUP_ * COUP_ + (size_t)COUP_ * COUP_;
            const __nv_bfloat16* wh1l = g_whl + (size_t)f * NBL_ * COUP_ * COUP_ + (size_t)COUP_ * COUP_;
            gemm_tile(g_HBh, g_HBl, wh1h, wh1l,
                      bh + (size_t)f * NBL_ * COUP_ + COUP_, nullptr, 0,
                      g_HAh, g_HAl, COUP_, COUP_,
                      COUP_, 1.0f, 1, m * 128, n * 128, smem);
            __syncthreads();
            __threadfence();
            if (tid == 0) atomicAdd(ctrF + 3 * 64 + m, 1);
            continue;
        }
        if (v < 2048) {                                 // G5: 0.1*(H @ wo^T + bo), K=1024
            int v5 = v - 1792;
            int m = v5 >> 2, n = v5 & 3;
            if (tid == 0) { while (ld_vol(ctrF + 3 * 64 + m) < 8) __nanosleep(200); __threadfence(); }
            __syncthreads();
            gemm_tile(g_HAh, g_HAl,
                      g_woh + (size_t)f * 2 * D2_ * COUP_, g_wol + (size_t)f * 2 * D2_ * COUP_,
                      bo + (size_t)f * 2 * D2_, g_Abuf, C_,
                      nullptr, nullptr, 0, 0,
                      COUP_, 0.1f, 0, m * 128, n * 128, smem);
            __syncthreads();
            __threadfence();
            if (tid == 0) atomicAdd(ctrF + 4 * 64 + m, 1);
            continue;
        }
        {                                               // coupling, 128 rows
            int m = v - 2048;
            if (tid == 0) { while (ld_vol(ctrF + 4 * 64 + m) < 4) __nanosleep(200); __threadfence(); }
            __syncthreads();
            coupling_rows(f, m * 128, off, out);
            __syncthreads();
            __threadfence();
            if (tid == 0) atomicAdd(ctrF + 5 * 64 + m, 1);
            continue;
        }
    }
}

// ---------------------------------------------------------------------------
extern "C" void kernel_launch(void* const* d_in, const int* in_sizes, int n_in,
                              void* d_out, int out_size) {
    const float* z0  = (const float*)d_in[0];
    const float* Wp  = (const float*)d_in[1];
    const float* g   = (const float*)d_in[2];
    const float* off = (const float*)d_in[3];
    const float* w0  = (const float*)d_in[4];
    const float* b0  = (const float*)d_in[5];
    const float* wh  = (const float*)d_in[6];
    const float* bh  = (const float*)d_in[7];
    const float* wo  = (const float*)d_in[8];
    const float* bo  = (const float*)d_in[9];
    float* out = (float*)d_out;

    cudaFuncSetAttribute(flow_persistent, cudaFuncAttributeMaxDynamicSharedMemorySize, SM_TOTAL);

    zero_sched_kernel<<<(F_ * 6 * 64 + 255) / 256, 256>>>();
    flow_persistent<<<296, 256, SM_TOTAL>>>(z0, Wp, g, off, w0, b0, wh, bh, wo, bo, out);
}

// round 12
// speedup vs baseline: 2.0239x; 2.0239x over previous
#include <cuda_runtime.h>
#include <cuda_bf16.h>
#include <cstdint>
#include <math.h>

// Problem constants
#define B_    8192
#define C_    512
#define F_    8
#define COUP_ 1024
#define NBL_  2
#define D1_   256
#define D2_   256

// ---------------------------------------------------------------------------
// Scratch (device globals — no allocations allowed)
// ---------------------------------------------------------------------------
__device__ float g_X0[B_ * C_];
__device__ float g_X1[B_ * C_];
__device__ float g_Abuf[B_ * C_];
__device__ float g_LD[B_];
__device__ float g_scale[F_ * C_];
__device__ float g_lssum[F_];

// split-bf16 weight planes
__device__ __nv_bfloat16 g_Wph[F_ * C_ * C_],              g_Wpl[F_ * C_ * C_];
__device__ __nv_bfloat16 g_w0h[F_ * COUP_ * D1_],          g_w0l[F_ * COUP_ * D1_];
__device__ __nv_bfloat16 g_whh[F_ * NBL_ * COUP_ * COUP_], g_whl[F_ * NBL_ * COUP_ * COUP_];
__device__ __nv_bfloat16 g_woh[F_ * 2 * D2_ * COUP_],      g_wol[F_ * 2 * D2_ * COUP_];

// split-bf16 activation planes
__device__ __nv_bfloat16 g_XFh[B_ * C_],    g_XFl[B_ * C_];
__device__ __nv_bfloat16 g_XAh[B_ * D1_],   g_XAl[B_ * D1_];
__device__ __nv_bfloat16 g_HAh[B_ * COUP_], g_HAl[B_ * COUP_];
__device__ __nv_bfloat16 g_HBh[B_ * COUP_], g_HBl[B_ * COUP_];

// ---------------------------------------------------------------------------
// Helpers
// ---------------------------------------------------------------------------
__device__ __forceinline__ uint32_t smem_u32(const void* p) {
    uint32_t a;
    asm("{ .reg .u64 t; cvta.to.shared.u64 t, %1; cvt.u32.u64 %0, t; }" : "=r"(a) : "l"(p));
    return a;
}
__device__ __forceinline__ void cpasync16(uint32_t s, const void* g) {
    asm volatile("cp.async.cg.shared.global [%0], [%1], 16;" :: "r"(s), "l"(g) : "memory");
}
__device__ __forceinline__ void cp_commit() { asm volatile("cp.async.commit_group;" ::: "memory"); }
__device__ __forceinline__ void cp_wait0()  { asm volatile("cp.async.wait_group 0;" ::: "memory"); }
__device__ __forceinline__ void cp_wait1()  { asm volatile("cp.async.wait_group 1;" ::: "memory"); }
__device__ __forceinline__ void ldsm4(uint32_t* r, uint32_t addr) {
    asm volatile("ldmatrix.sync.aligned.m8n8.x4.shared.b16 {%0,%1,%2,%3}, [%4];"
                 : "=r"(r[0]), "=r"(r[1]), "=r"(r[2]), "=r"(r[3]) : "r"(addr));
}
__device__ __forceinline__ void mma16816(float* d, const uint32_t* a, const uint32_t* b) {
    asm("mma.sync.aligned.m16n8k16.row.col.f32.bf16.bf16.f32 "
        "{%0,%1,%2,%3}, {%4,%5,%6,%7}, {%8,%9}, {%0,%1,%2,%3};"
        : "+f"(d[0]), "+f"(d[1]), "+f"(d[2]), "+f"(d[3])
        : "r"(a[0]), "r"(a[1]), "r"(a[2]), "r"(a[3]), "r"(b[0]), "r"(b[1]));
}
__device__ __forceinline__ uint32_t pk2(__nv_bfloat16 a, __nv_bfloat16 b) {
    return (uint32_t)__bfloat16_as_ushort(a) | ((uint32_t)__bfloat16_as_ushort(b) << 16);
}

// smem: CTA tile 128(M) x 256(N) x 32(K). 64B per row-chunk, swizzle c^((r>>1)&3)
// stage = A_hi(8K) A_lo(8K) B_hi(16K) B_lo(16K) = 48KB; 3 stages = 144KB
#define A_PLANE 8192
#define B_PLANE 16384
#define STAGE_BYTES 49152
#define NSTAGE 3
#define SM_BIAS_OFF (NSTAGE * STAGE_BYTES)      // 147456
#define SM_TOTAL (SM_BIAS_OFF + 1024)           // 148480 -> 1 CTA/SM

// ---------------------------------------------------------------------------
// Split-bf16 GEMM via mma.sync (HMMA):
//   Y[M=8192, N] = act(alpha * (A @ B^T + bias))
//   CTA tile 128x256x32, 256 threads, warp grid 2(m) x 4(n), warp tile 64x64
//   -> 2x less smem fragment traffic & L2 demand per output than 128x128
// ---------------------------------------------------------------------------
template <int OUT_F32, int OUT_SPLIT, int RELU>
__global__ __launch_bounds__(256, 1)
void mma_gemm(const __nv_bfloat16* __restrict__ Ah, const __nv_bfloat16* __restrict__ Al,
              const __nv_bfloat16* __restrict__ Bh, const __nv_bfloat16* __restrict__ Bl,
              const float* __restrict__ bias,
              float* __restrict__ Yf, int ldy,
              __nv_bfloat16* __restrict__ Oh, __nv_bfloat16* __restrict__ Ol,
              int ldo, int split_w,
              int K, float alpha) {
    extern __shared__ char smem[];
    const uint32_t sb = smem_u32(smem);
    const int tid  = threadIdx.x;
    const int lane = tid & 31;
    const int wid  = tid >> 5;
    const int warp_m = wid & 1;         // 2 warps along M (64 rows each)
    const int warp_n = wid >> 1;        // 4 warps along N (64 cols each)
    const int m0 = blockIdx.y * 128;
    const int n0 = blockIdx.x * 256;

    float* bias_s = (float*)(smem + SM_BIAS_OFF);
    for (int j = tid; j < 256; j += 256) bias_s[j] = bias ? bias[n0 + j] : 0.0f;

    float acc[4][8][4];
#pragma unroll
    for (int mt = 0; mt < 4; mt++)
#pragma unroll
        for (int nt = 0; nt < 8; nt++)
#pragma unroll
            for (int q = 0; q < 4; q++) acc[mt][nt][q] = 0.0f;

    const int nchunks = K >> 5;

    auto prefetch = [&](int st, int kb) {
        uint32_t base = sb + st * STAGE_BYTES;
        // A: 128 rows x 64B per plane = 512 x 16B vectors
#pragma unroll
        for (int i = 0; i < 2; i++) {
            int v = tid + i * 256;            // 0..511
            int r = v >> 2, c = v & 3;
            uint32_t sw = (uint32_t)((c ^ ((r >> 1) & 3)) << 4) + r * 64;
            size_t ga = (size_t)(m0 + r) * K + kb + c * 8;
            cpasync16(base + sw,           Ah + ga);
            cpasync16(base + A_PLANE + sw, Al + ga);
        }
        // B: 256 rows x 64B per plane = 1024 x 16B vectors
#pragma unroll
        for (int i = 0; i < 4; i++) {
            int v = tid + i * 256;            // 0..1023
            int r = v >> 2, c = v & 3;
            uint32_t sw = (uint32_t)((c ^ ((r >> 1) & 3)) << 4) + r * 64;
            size_t gb = (size_t)(n0 + r) * K + kb + c * 8;
            cpasync16(base + 2 * A_PLANE + sw,           Bh + gb);
            cpasync16(base + 2 * A_PLANE + B_PLANE + sw, Bl + gb);
        }
        cp_commit();
    };

    auto compute = [&](int st) {
        uint32_t base = sb + st * STAGE_BYTES;
#pragma unroll
        for (int ks = 0; ks < 2; ks++) {
            uint32_t ah[4][4], al_[4][4];
#pragma unroll
            for (int mt = 0; mt < 4; mt++) {
                int gq  = lane >> 3;
                int row = warp_m * 64 + mt * 16 + (lane & 7) + (gq & 1) * 8;
                int ch  = ks * 2 + (gq >> 1);
                uint32_t o = row * 64 + ((ch ^ ((row >> 1) & 3)) << 4);
                ldsm4(ah[mt],  base + o);
                ldsm4(al_[mt], base + A_PLANE + o);
            }
            uint32_t bh_[4][4], bl_[4][4];
#pragma unroll
            for (int nt = 0; nt < 4; nt++) {
                int row = warp_n * 64 + nt * 16 + (lane & 7) + ((lane >> 4) & 1) * 8;
                int ch  = ks * 2 + ((lane >> 3) & 1);
                uint32_t o = row * 64 + ((ch ^ ((row >> 1) & 3)) << 4);
                ldsm4(bh_[nt], base + 2 * A_PLANE + o);
                ldsm4(bl_[nt], base + 2 * A_PLANE + B_PLANE + o);
            }
            // Pass 1: Ah*Bh
#pragma unroll
            for (int mt = 0; mt < 4; mt++)
#pragma unroll
                for (int nt = 0; nt < 4; nt++)
#pragma unroll
                    for (int hf = 0; hf < 2; hf++)
                        mma16816(acc[mt][nt * 2 + hf], ah[mt], &bh_[nt][hf * 2]);
            // Pass 2: Ah*Bl
#pragma unroll
            for (int mt = 0; mt < 4; mt++)
#pragma unroll
                for (int nt = 0; nt < 4; nt++)
#pragma unroll
                    for (int hf = 0; hf < 2; hf++)
                        mma16816(acc[mt][nt * 2 + hf], ah[mt], &bl_[nt][hf * 2]);
            // Pass 3: Al*Bh
#pragma unroll
            for (int mt = 0; mt < 4; mt++)
#pragma unroll
                for (int nt = 0; nt < 4; nt++)
#pragma unroll
                    for (int hf = 0; hf < 2; hf++)
                        mma16816(acc[mt][nt * 2 + hf], al_[mt], &bh_[nt][hf * 2]);
        }
    };

    // 3-stage pipeline, 1 sync per chunk
    prefetch(0, 0);
    prefetch(1, 32);
    for (int kc = 0; kc < nchunks; kc++) {
        if (kc + 1 < nchunks) cp_wait1();
        else                  cp_wait0();
        __syncthreads();
        if (kc + 2 < nchunks) prefetch((kc + 2) % 3, (kc + 2) * 32);
        compute(kc % 3);
    }

    // ---- epilogue --------------------------------------------------------
    const int qr  = lane >> 2;
    const int qc2 = (lane & 3) * 2;
#pragma unroll
    for (int mt = 0; mt < 4; mt++) {
        int r0 = m0 + warp_m * 64 + mt * 16 + qr;
        int r1 = r0 + 8;
#pragma unroll
        for (int nt = 0; nt < 8; nt++) {
            float* d = acc[mt][nt];
            int col_l = warp_n * 64 + nt * 8 + qc2;
            int col_g = n0 + col_l;
            float bb0 = bias_s[col_l], bb1 = bias_s[col_l + 1];
            float v00 = (d[0] + bb0) * alpha;
            float v01 = (d[1] + bb1) * alpha;
            float v10 = (d[2] + bb0) * alpha;
            float v11 = (d[3] + bb1) * alpha;
            if (RELU) {
                v00 = fmaxf(v00, 0.0f); v01 = fmaxf(v01, 0.0f);
                v10 = fmaxf(v10, 0.0f); v11 = fmaxf(v11, 0.0f);
            }
            if (OUT_F32) {
                *(float2*)(Yf + (size_t)r0 * ldy + col_g) = make_float2(v00, v01);
                *(float2*)(Yf + (size_t)r1 * ldy + col_g) = make_float2(v10, v11);
            }
            if (OUT_SPLIT && col_g < split_w) {
                __nv_bfloat16 h00 = __float2bfloat16(v00), h01 = __float2bfloat16(v01);
                __nv_bfloat16 h10 = __float2bfloat16(v10), h11 = __float2bfloat16(v11);
                __nv_bfloat16 l00 = __float2bfloat16(v00 - __bfloat162float(h00));
                __nv_bfloat16 l01 = __float2bfloat16(v01 - __bfloat162float(h01));
                __nv_bfloat16 l10 = __float2bfloat16(v10 - __bfloat162float(h10));
                __nv_bfloat16 l11 = __float2bfloat16(v11 - __bfloat162float(h11));
                *(uint32_t*)(Oh + (size_t)r0 * ldo + col_g) = pk2(h00, h01);
                *(uint32_t*)(Oh + (size_t)r1 * ldo + col_g) = pk2(h10, h11);
                *(uint32_t*)(Ol + (size_t)r0 * ldo + col_g) = pk2(l00, l01);
                *(uint32_t*)(Ol + (size_t)r1 * ldo + col_g) = pk2(l10, l11);
            }
        }
    }
}

// ---------------------------------------------------------------------------
// Fused weight split
// ---------------------------------------------------------------------------
#define N_WP (F_ * C_ * C_)
#define N_W0 (F_ * COUP_ * D1_)
#define N_WH (F_ * NBL_ * COUP_ * COUP_)
#define N_WO (F_ * 2 * D2_ * COUP_)
#define N_SPLIT_TOTAL (N_WP + N_W0 + N_WH + N_WO)

__global__ void split_all_kernel(const float* __restrict__ Wp,
                                 const float* __restrict__ w0,
                                 const float* __restrict__ wh,
                                 const float* __restrict__ wo) {
    int i = blockIdx.x * blockDim.x + threadIdx.x;
    if (i >= N_SPLIT_TOTAL) return;
    const float* src;
    __nv_bfloat16 *hi, *lo;
    int j = i;
    if (j < N_WP) {
        src = Wp; hi = g_Wph; lo = g_Wpl;
    } else if ((j -= N_WP) < N_W0) {
        src = w0; hi = g_w0h; lo = g_w0l;
    } else if ((j -= N_W0) < N_WH) {
        src = wh; hi = g_whh; lo = g_whl;
    } else {
        j -= N_WH;
        src = wo; hi = g_woh; lo = g_wol;
    }
    float v = src[j];
    __nv_bfloat16 h = __float2bfloat16(v);
    hi[j] = h;
    lo[j] = __float2bfloat16(v - __bfloat162float(h));
}

__global__ void prep_scale_kernel(const float* __restrict__ g) {
    int f = blockIdx.x;
    int c = threadIdx.x;
    float gv = g[f * C_ + c];
    float sc = 0.2f * log1pf(expf(0.5f * gv));
    g_scale[f * C_ + c] = sc;
    __shared__ float red[C_];
    red[c] = logf(sc);
    __syncthreads();
    for (int s = C_ / 2; s > 0; s >>= 1) {
        if (c < s) red[c] += red[c + s];
        __syncthreads();
    }
    if (c == 0) g_lssum[f] = red[0];
}

// flow-0 input prep: XF = split(z0 * scale0 + off0)
__global__ void prep0_full_kernel(const float* __restrict__ z0,
                                  const float* __restrict__ off0) {
    int i = blockIdx.x * blockDim.x + threadIdx.x;
    if (i < B_ * C_) {
        int c = i & (C_ - 1);
        float v = fmaf(z0[i], g_scale[c], off0[c]);
        __nv_bfloat16 h = __float2bfloat16(v);
        g_XFh[i] = h;
        g_XFl[i] = __float2bfloat16(v - __bfloat162float(h));
    }
}

// ---------------------------------------------------------------------------
// Coupling + log-det + next-flow input prep (or final output write)
// ---------------------------------------------------------------------------
__global__ __launch_bounds__(256)
void coupling_kernel(float* __restrict__ X, int f,
                     const float* __restrict__ scale_next,
                     const float* __restrict__ off_next,
                     int do_next,
                     float* __restrict__ out_final) {
    int warp = threadIdx.x >> 5;
    int lane = threadIdx.x & 31;
    int row  = blockIdx.x * 8 + warp;
    const float* arow = g_Abuf + (size_t)row * C_;
    float*       xrow = X + (size_t)row * C_;
    __nv_bfloat16* fh = g_XFh + (size_t)row * C_;
    __nv_bfloat16* fl = g_XFl + (size_t)row * C_;
    float* orow = out_final ? (out_final + (size_t)row * C_) : nullptr;

    float sum = 0.0f;
#pragma unroll
    for (int it = 0; it < 8; it++) {
        int c = lane + it * 32;
        float s  = 2.0f * tanhf(arow[c]);
        float t  = arow[D1_ + c];
        float x2 = xrow[D1_ + c] * expf(s) + t;
        xrow[D1_ + c] = x2;
        sum += s;
        float x1v = xrow[c];
        if (do_next) {
            float v1 = fmaf(x1v, scale_next[c],        off_next[c]);
            float v2 = fmaf(x2,  scale_next[D1_ + c],  off_next[D1_ + c]);
            __nv_bfloat16 h1 = __float2bfloat16(v1);
            __nv_bfloat16 h2 = __float2bfloat16(v2);
            fh[c]        = h1;
            fh[D1_ + c]  = h2;
            fl[c]        = __float2bfloat16(v1 - __bfloat162float(h1));
            fl[D1_ + c]  = __float2bfloat16(v2 - __bfloat162float(h2));
        }
        if (orow) {
            orow[c]       = x1v;
            orow[D1_ + c] = x2;
        }
    }
#pragma unroll
    for (int o = 16; o > 0; o >>= 1)
        sum += __shfl_down_sync(0xFFFFFFFFu, sum, o);
    if (lane == 0) {
        float prev = (f == 0) ? 0.0f : g_LD[row];
        float ld = prev + sum + g_lssum[f];
        g_LD[row] = ld;
        if (out_final) out_final[(size_t)B_ * C_ + row] = ld;
    }
}

// ---------------------------------------------------------------------------
extern "C" void kernel_launch(void* const* d_in, const int* in_sizes, int n_in,
                              void* d_out, int out_size) {
    const float* z0  = (const float*)d_in[0];
    const float* Wp  = (const float*)d_in[1];
    const float* g   = (const float*)d_in[2];
    const float* off = (const float*)d_in[3];
    const float* w0  = (const float*)d_in[4];
    const float* b0  = (const float*)d_in[5];
    const float* wh  = (const float*)d_in[6];
    const float* bh  = (const float*)d_in[7];
    const float* wo  = (const float*)d_in[8];
    const float* bo  = (const float*)d_in[9];
    float* out = (float*)d_out;

    float *X0, *X1, *Abuf, *scaleP;
    __nv_bfloat16 *Wph, *Wpl, *w0h, *w0l, *whh, *whl, *woh, *wol;
    __nv_bfloat16 *XFh, *XFl, *XAh, *XAl, *HAh, *HAl, *HBh, *HBl;
    cudaGetSymbolAddress((void**)&X0, g_X0);
    cudaGetSymbolAddress((void**)&X1, g_X1);
    cudaGetSymbolAddress((void**)&Abuf, g_Abuf);
    cudaGetSymbolAddress((void**)&scaleP, g_scale);
    cudaGetSymbolAddress((void**)&Wph, g_Wph); cudaGetSymbolAddress((void**)&Wpl, g_Wpl);
    cudaGetSymbolAddress((void**)&w0h, g_w0h); cudaGetSymbolAddress((void**)&w0l, g_w0l);
    cudaGetSymbolAddress((void**)&whh, g_whh); cudaGetSymbolAddress((void**)&whl, g_whl);
    cudaGetSymbolAddress((void**)&woh, g_woh); cudaGetSymbolAddress((void**)&wol, g_wol);
    cudaGetSymbolAddress((void**)&XFh, g_XFh); cudaGetSymbolAddress((void**)&XFl, g_XFl);
    cudaGetSymbolAddress((void**)&XAh, g_XAh); cudaGetSymbolAddress((void**)&XAl, g_XAl);
    cudaGetSymbolAddress((void**)&HAh, g_HAh); cudaGetSymbolAddress((void**)&HAl, g_HAl);
    cudaGetSymbolAddress((void**)&HBh, g_HBh); cudaGetSymbolAddress((void**)&HBl, g_HBl);

    cudaFuncSetAttribute(mma_gemm<1,1,0>, cudaFuncAttributeMaxDynamicSharedMemorySize, SM_TOTAL);
    cudaFuncSetAttribute(mma_gemm<0,1,1>, cudaFuncAttributeMaxDynamicSharedMemorySize, SM_TOTAL);
    cudaFuncSetAttribute(mma_gemm<1,0,0>, cudaFuncAttributeMaxDynamicSharedMemorySize, SM_TOTAL);

    // launch order: 0=prep_scale, 1=split_all, 2=prep0, 3=G1, 4=G2, 5=G3 (ncu)
    prep_scale_kernel<<<F_, C_>>>(g);
    split_all_kernel<<<(N_SPLIT_TOTAL + 255) / 256, 256>>>(Wp, w0, wh, wo);
    prep0_full_kernel<<<(B_ * C_ + 255) / 256, 256>>>(z0, off);

    for (int f = 0; f < F_; f++) {
        float* Xcur = (f & 1) ? X1 : X0;

        const __nv_bfloat16* Wph_f = Wph + (size_t)f * C_ * C_;
        const __nv_bfloat16* Wpl_f = Wpl + (size_t)f * C_ * C_;
        const __nv_bfloat16* w0h_f = w0h + (size_t)f * COUP_ * D1_;
        const __nv_bfloat16* w0l_f = w0l + (size_t)f * COUP_ * D1_;
        const __nv_bfloat16* whh0  = whh + (size_t)f * NBL_ * COUP_ * COUP_;
        const __nv_bfloat16* whl0  = whl + (size_t)f * NBL_ * COUP_ * COUP_;
        const __nv_bfloat16* whh1  = whh0 + (size_t)COUP_ * COUP_;
        const __nv_bfloat16* whl1  = whl0 + (size_t)COUP_ * COUP_;
        const __nv_bfloat16* woh_f = woh + (size_t)f * 2 * D2_ * COUP_;
        const __nv_bfloat16* wol_f = wol + (size_t)f * 2 * D2_ * COUP_;
        const float* b0_f  = b0 + (size_t)f * COUP_;
        const float* bh_f0 = bh + (size_t)f * NBL_ * COUP_;
        const float* bh_f1 = bh_f0 + COUP_;
        const float* bo_f  = bo + (size_t)f * 2 * D2_;

        // 1) X = XF @ Wp^T ; fp32 out + x1 split planes  (N=512 -> 2x64 CTAs)
        mma_gemm<1,1,0><<<dim3(C_ / 256, B_ / 128), 256, SM_TOTAL>>>(
            XFh, XFl, Wph_f, Wpl_f, nullptr,
            Xcur, C_, XAh, XAl, D1_, D1_, C_, 1.0f);

        // 2) H = relu(x1 @ w0^T + b0)   (N=1024 -> 4x64 CTAs)
        mma_gemm<0,1,1><<<dim3(COUP_ / 256, B_ / 128), 256, SM_TOTAL>>>(
            XAh, XAl, w0h_f, w0l_f, b0_f,
            nullptr, 0, HAh, HAl, COUP_, COUP_, D1_, 1.0f);

        // 3) H' = relu(H @ wh0^T + bh0)
        mma_gemm<0,1,1><<<dim3(COUP_ / 256, B_ / 128), 256, SM_TOTAL>>>(
            HAh, HAl, whh0, whl0, bh_f0,
            nullptr, 0, HBh, HBl, COUP_, COUP_, COUP_, 1.0f);

        // 4) H = relu(H' @ wh1^T + bh1)
        mma_gemm<0,1,1><<<dim3(COUP_ / 256, B_ / 128), 256, SM_TOTAL>>>(
            HBh, HBl, whh1, whl1, bh_f1,
            nullptr, 0, HAh, HAl, COUP_, COUP_, COUP_, 1.0f);

        // 5) a = 0.1*(H @ wo^T + bo) ; fp32 out
        mma_gemm<1,0,0><<<dim3((2 * D2_) / 256, B_ / 128), 256, SM_TOTAL>>>(
            HAh, HAl, woh_f, wol_f, bo_f,
            Abuf, C_, nullptr, nullptr, 0, 0, COUP_, 0.1f);

        // 6) coupling + log-det + next-flow prep (or final output write)
        int do_next = (f + 1 < F_) ? 1 : 0;
        const float* sc_n  = scaleP + (size_t)((f + 1) % F_) * C_;
        const float* off_n = off + (size_t)((f + 1) % F_) * C_;
        float* out_final = (f == F_ - 1) ? out : nullptr;
        coupling_kernel<<<B_ / 8, 256>>>(Xcur, f, sc_n, off_n, do_next, out_final);
    }
}

// round 13
// speedup vs baseline: 2.0563x; 1.0160x over previous
#include <cuda_runtime.h>
#include <cuda_bf16.h>
#include <cstdint>
#include <math.h>

// Problem constants
#define B_    8192
#define C_    512
#define F_    8
#define COUP_ 1024
#define NBL_  2
#define D1_   256
#define D2_   256

// ---------------------------------------------------------------------------
// Scratch (device globals — no allocations allowed)
// ---------------------------------------------------------------------------
__device__ float g_X0[B_ * C_];
__device__ float g_X1[B_ * C_];
__device__ float g_LD[B_];
__device__ float g_scale[F_ * C_];
__device__ float g_lssum[F_];

// split-bf16 weight planes (wo stored ROW-PERMUTED: new row 2j = old j (s),
// new row 2j+1 = old j+256 (t))
__device__ __nv_bfloat16 g_Wph[F_ * C_ * C_],              g_Wpl[F_ * C_ * C_];
__device__ __nv_bfloat16 g_w0h[F_ * COUP_ * D1_],          g_w0l[F_ * COUP_ * D1_];
__device__ __nv_bfloat16 g_whh[F_ * NBL_ * COUP_ * COUP_], g_whl[F_ * NBL_ * COUP_ * COUP_];
__device__ __nv_bfloat16 g_woh[F_ * 2 * D2_ * COUP_],      g_wol[F_ * 2 * D2_ * COUP_];

// split-bf16 activation planes; XF ping-pong across flows
__device__ __nv_bfloat16 g_XF0h[B_ * C_],   g_XF0l[B_ * C_];
__device__ __nv_bfloat16 g_XF1h[B_ * C_],   g_XF1l[B_ * C_];
__device__ __nv_bfloat16 g_XAh[B_ * D1_],   g_XAl[B_ * D1_];
__device__ __nv_bfloat16 g_HAh[B_ * COUP_], g_HAl[B_ * COUP_];
__device__ __nv_bfloat16 g_HBh[B_ * COUP_], g_HBl[B_ * COUP_];

// ---------------------------------------------------------------------------
// Helpers
// ---------------------------------------------------------------------------
__device__ __forceinline__ uint32_t smem_u32(const void* p) {
    uint32_t a;
    asm("{ .reg .u64 t; cvta.to.shared.u64 t, %1; cvt.u32.u64 %0, t; }" : "=r"(a) : "l"(p));
    return a;
}
__device__ __forceinline__ void cpasync16(uint32_t s, const void* g) {
    asm volatile("cp.async.cg.shared.global [%0], [%1], 16;" :: "r"(s), "l"(g) : "memory");
}
__device__ __forceinline__ void cp_commit() { asm volatile("cp.async.commit_group;" ::: "memory"); }
__device__ __forceinline__ void cp_wait0()  { asm volatile("cp.async.wait_group 0;" ::: "memory"); }
__device__ __forceinline__ void cp_wait1()  { asm volatile("cp.async.wait_group 1;" ::: "memory"); }
__device__ __forceinline__ void ldsm4(uint32_t* r, uint32_t addr) {
    asm volatile("ldmatrix.sync.aligned.m8n8.x4.shared.b16 {%0,%1,%2,%3}, [%4];"
                 : "=r"(r[0]), "=r"(r[1]), "=r"(r[2]), "=r"(r[3]) : "r"(addr));
}
__device__ __forceinline__ void mma16816(float* d, const uint32_t* a, const uint32_t* b) {
    asm("mma.sync.aligned.m16n8k16.row.col.f32.bf16.bf16.f32 "
        "{%0,%1,%2,%3}, {%4,%5,%6,%7}, {%8,%9}, {%0,%1,%2,%3};"
        : "+f"(d[0]), "+f"(d[1]), "+f"(d[2]), "+f"(d[3])
        : "r"(a[0]), "r"(a[1]), "r"(a[2]), "r"(a[3]), "r"(b[0]), "r"(b[1]));
}
__device__ __forceinline__ uint32_t pk2(__nv_bfloat16 a, __nv_bfloat16 b) {
    return (uint32_t)__bfloat16_as_ushort(a) | ((uint32_t)__bfloat16_as_ushort(b) << 16);
}
__device__ __forceinline__ void split_store(__nv_bfloat16* hp, __nv_bfloat16* lp,
                                            float a, float b) {
    __nv_bfloat16 ha = __float2bfloat16(a), hb = __float2bfloat16(b);
    *(uint32_t*)hp = pk2(ha, hb);
    *(uint32_t*)lp = pk2(__float2bfloat16(a - __bfloat162float(ha)),
                         __float2bfloat16(b - __bfloat162float(hb)));
}

// smem tile layout: 128 rows x 32 bf16 (64B/row), 16B chunk swizzle: c^((r>>1)&3)
#define TILE_BYTES 8192
#define STAGE_BYTES 32768           // A_hi, A_lo, B_hi, B_lo
#define NSTAGE 3
#define SM_BIAS_OFF (NSTAGE * STAGE_BYTES)      // 98304
#define SM_TOTAL (SM_BIAS_OFF + 512)            // 98816 -> 2 CTAs/SM

// MODE: 0 = G1 (X out + XA split + XFnext x1-part), 1 = mid relu+split,
//       2 = G5 fused coupling epilogue
// ---------------------------------------------------------------------------
template <int MODE>
__global__ __launch_bounds__(256)
void mma_gemm(const __nv_bfloat16* __restrict__ Ah, const __nv_bfloat16* __restrict__ Al,
              const __nv_bfloat16* __restrict__ Bh, const __nv_bfloat16* __restrict__ Bl,
              const float* __restrict__ bias,
              float* __restrict__ Yf, int ldy,
              __nv_bfloat16* __restrict__ Oh, __nv_bfloat16* __restrict__ Ol,
              int ldo, int split_w, int K,
              const float* __restrict__ scn,  const float* __restrict__ offn,
              __nv_bfloat16* __restrict__ xfnh, __nv_bfloat16* __restrict__ xfnl,
              const float* __restrict__ Xc,
              float* __restrict__ outp, int last) {
    extern __shared__ char smem[];
    const uint32_t sb = smem_u32(smem);
    const int tid  = threadIdx.x;
    const int lane = tid & 31;
    const int wid  = tid >> 5;
    const int warp_m = wid & 3;
    const int warp_n = wid >> 2;
    const int m0 = blockIdx.y * 128;
    const int n0 = blockIdx.x * 128;

    float* bias_s = (float*)(smem + SM_BIAS_OFF);
    for (int j = tid; j < 128; j += 256) {
        if (MODE == 2) {
            int rn = n0 + j;
            int old = (rn & 1) ? ((rn >> 1) + 256) : (rn >> 1);
            bias_s[j] = bias[old];
        } else {
            bias_s[j] = bias ? bias[n0 + j] : 0.0f;
        }
    }

    float acc[2][8][4];
#pragma unroll
    for (int mt = 0; mt < 2; mt++)
#pragma unroll
        for (int nt = 0; nt < 8; nt++)
#pragma unroll
            for (int q = 0; q < 4; q++) acc[mt][nt][q] = 0.0f;

    const int nchunks = K >> 5;

    auto prefetch = [&](int st, int kb) {
        uint32_t base = sb + st * STAGE_BYTES;
#pragma unroll
        for (int i = 0; i < 2; i++) {
            int v = tid + i * 256;
            int r = v >> 2, c = v & 3;
            uint32_t sw = (uint32_t)((c ^ ((r >> 1) & 3)) << 4) + r * 64;
            size_t ga = (size_t)(m0 + r) * K + kb + c * 8;
            size_t gb = (size_t)(n0 + r) * K + kb + c * 8;
            cpasync16(base + sw,                  Ah + ga);
            cpasync16(base + TILE_BYTES + sw,     Al + ga);
            cpasync16(base + 2 * TILE_BYTES + sw, Bh + gb);
            cpasync16(base + 3 * TILE_BYTES + sw, Bl + gb);
        }
        cp_commit();
    };

    auto compute = [&](int st) {
        uint32_t base = sb + st * STAGE_BYTES;
#pragma unroll
        for (int ks = 0; ks < 2; ks++) {
            uint32_t ah[2][4], al_[2][4];
#pragma unroll
            for (int mt = 0; mt < 2; mt++) {
                int gq  = lane >> 3;
                int row = warp_m * 32 + mt * 16 + (lane & 7) + (gq & 1) * 8;
                int ch  = ks * 2 + (gq >> 1);
                uint32_t o = row * 64 + ((ch ^ ((row >> 1) & 3)) << 4);
                ldsm4(ah[mt],  base + o);
                ldsm4(al_[mt], base + TILE_BYTES + o);
            }
            uint32_t bh_[4][4], bl_[4][4];
#pragma unroll
            for (int nt = 0; nt < 4; nt++) {
                int row = warp_n * 64 + nt * 16 + (lane & 7) + ((lane >> 4) & 1) * 8;
                int ch  = ks * 2 + ((lane >> 3) & 1);
                uint32_t o = row * 64 + ((ch ^ ((row >> 1) & 3)) << 4);
                ldsm4(bh_[nt], base + 2 * TILE_BYTES + o);
                ldsm4(bl_[nt], base + 3 * TILE_BYTES + o);
            }
#pragma unroll
            for (int mt = 0; mt < 2; mt++)
#pragma unroll
                for (int nt = 0; nt < 4; nt++)
#pragma unroll
                    for (int hf = 0; hf < 2; hf++)
                        mma16816(acc[mt][nt * 2 + hf], ah[mt], &bh_[nt][hf * 2]);
#pragma unroll
            for (int mt = 0; mt < 2; mt++)
#pragma unroll
                for (int nt = 0; nt < 4; nt++)
#pragma unroll
                    for (int hf = 0; hf < 2; hf++)
                        mma16816(acc[mt][nt * 2 + hf], ah[mt], &bl_[nt][hf * 2]);
#pragma unroll
            for (int mt = 0; mt < 2; mt++)
#pragma unroll
                for (int nt = 0; nt < 4; nt++)
#pragma unroll
                    for (int hf = 0; hf < 2; hf++)
                        mma16816(acc[mt][nt * 2 + hf], al_[mt], &bh_[nt][hf * 2]);
        }
    };

    prefetch(0, 0);
    prefetch(1, 32);
    for (int kc = 0; kc < nchunks; kc++) {
        if (kc + 1 < nchunks) cp_wait1();
        else                  cp_wait0();
        __syncthreads();
        if (kc + 2 < nchunks) prefetch((kc + 2) % 3, (kc + 2) * 32);
        compute(kc % 3);
    }

    // ---- epilogue --------------------------------------------------------
    const int qr  = lane >> 2;
    const int qc2 = (lane & 3) * 2;

#pragma unroll
    for (int mt = 0; mt < 2; mt++) {
        int r0 = m0 + warp_m * 32 + mt * 16 + qr;
        int r1 = r0 + 8;
        float sum_s0 = 0.0f, sum_s1 = 0.0f;   // MODE 2 row-sums of s
#pragma unroll
        for (int nt = 0; nt < 8; nt++) {
            float* d = acc[mt][nt];
            int col_l = warp_n * 64 + nt * 8 + qc2;
            int col_g = n0 + col_l;

            if (MODE == 2) {
                // pair (s_j, t_j): col_g = 2j, col_g+1 = 2j+1
                int jg = col_g >> 1;
                float bs = bias_s[col_l], bt = bias_s[col_l + 1];
                float s0 = 2.0f * tanhf((d[0] + bs) * 0.1f);
                float t0 = (d[1] + bt) * 0.1f;
                float s1 = 2.0f * tanhf((d[2] + bs) * 0.1f);
                float t1 = (d[3] + bt) * 0.1f;
                float nx0 = Xc[(size_t)r0 * C_ + D1_ + jg] * expf(s0) + t0;
                float nx1 = Xc[(size_t)r1 * C_ + D1_ + jg] * expf(s1) + t1;
                sum_s0 += s0;
                sum_s1 += s1;
                if (!last) {
                    float u0 = fmaf(nx0, scn[D1_ + jg], offn[D1_ + jg]);
                    float u1 = fmaf(nx1, scn[D1_ + jg], offn[D1_ + jg]);
                    __nv_bfloat16 h0 = __float2bfloat16(u0);
                    __nv_bfloat16 h1 = __float2bfloat16(u1);
                    xfnh[(size_t)r0 * C_ + D1_ + jg] = h0;
                    xfnh[(size_t)r1 * C_ + D1_ + jg] = h1;
                    xfnl[(size_t)r0 * C_ + D1_ + jg] = __float2bfloat16(u0 - __bfloat162float(h0));
                    xfnl[(size_t)r1 * C_ + D1_ + jg] = __float2bfloat16(u1 - __bfloat162float(h1));
                } else {
                    outp[(size_t)r0 * C_ + D1_ + jg] = nx0;
                    outp[(size_t)r1 * C_ + D1_ + jg] = nx1;
                }
            } else {
                float bb0 = bias_s[col_l], bb1 = bias_s[col_l + 1];
                float v00 = d[0] + bb0, v01 = d[1] + bb1;
                float v10 = d[2] + bb0, v11 = d[3] + bb1;
                if (MODE == 1) {
                    v00 = fmaxf(v00, 0.0f); v01 = fmaxf(v01, 0.0f);
                    v10 = fmaxf(v10, 0.0f); v11 = fmaxf(v11, 0.0f);
                    split_store(Oh + (size_t)r0 * ldo + col_g, Ol + (size_t)r0 * ldo + col_g, v00, v01);
                    split_store(Oh + (size_t)r1 * ldo + col_g, Ol + (size_t)r1 * ldo + col_g, v10, v11);
                } else { // MODE 0: G1
                    *(float2*)(Yf + (size_t)r0 * ldy + col_g) = make_float2(v00, v01);
                    *(float2*)(Yf + (size_t)r1 * ldy + col_g) = make_float2(v10, v11);
                    if (last) {
                        *(float2*)(outp + (size_t)r0 * ldy + col_g) = make_float2(v00, v01);
                        *(float2*)(outp + (size_t)r1 * ldy + col_g) = make_float2(v10, v11);
                    }
                    if (col_g < split_w) {
                        split_store(Oh + (size_t)r0 * ldo + col_g, Ol + (size_t)r0 * ldo + col_g, v00, v01);
                        split_store(Oh + (size_t)r1 * ldo + col_g, Ol + (size_t)r1 * ldo + col_g, v10, v11);
                        if (!last) {
                            float u00 = fmaf(v00, scn[col_g],     offn[col_g]);
                            float u01 = fmaf(v01, scn[col_g + 1], offn[col_g + 1]);
                            float u10 = fmaf(v10, scn[col_g],     offn[col_g]);
                            float u11 = fmaf(v11, scn[col_g + 1], offn[col_g + 1]);
                            split_store(xfnh + (size_t)r0 * C_ + col_g, xfnl + (size_t)r0 * C_ + col_g, u00, u01);
                            split_store(xfnh + (size_t)r1 * C_ + col_g, xfnl + (size_t)r1 * C_ + col_g, u10, u11);
                        }
                    }
                }
            }
        }
        if (MODE == 2) {
            // reduce s-sums across the 4 threads sharing each row (lane&3)
            sum_s0 += __shfl_xor_sync(0xFFFFFFFFu, sum_s0, 1);
            sum_s0 += __shfl_xor_sync(0xFFFFFFFFu, sum_s0, 2);
            sum_s1 += __shfl_xor_sync(0xFFFFFFFFu, sum_s1, 1);
            sum_s1 += __shfl_xor_sync(0xFFFFFFFFu, sum_s1, 2);
            if ((lane & 3) == 0) {
                atomicAdd(g_LD + r0, sum_s0);
                atomicAdd(g_LD + r1, sum_s1);
            }
        }
    }
}

// ---------------------------------------------------------------------------
// Fused weight split (wo permuted: new row 2j = old j, 2j+1 = old j+256)
// ---------------------------------------------------------------------------
#define N_WP (F_ * C_ * C_)
#define N_W0 (F_ * COUP_ * D1_)
#define N_WH (F_ * NBL_ * COUP_ * COUP_)
#define N_WO (F_ * 2 * D2_ * COUP_)
#define N_SPLIT_TOTAL (N_WP + N_W0 + N_WH + N_WO)

__global__ void split_all_kernel(const float* __restrict__ Wp,
                                 const float* __restrict__ w0,
                                 const float* __restrict__ wh,
                                 const float* __restrict__ wo) {
    int i = blockIdx.x * blockDim.x + threadIdx.x;
    if (i >= N_SPLIT_TOTAL) return;
    const float* src;
    __nv_bfloat16 *hi, *lo;
    int j = i;
    int dst;
    if (j < N_WP) {
        src = Wp; hi = g_Wph; lo = g_Wpl; dst = j;
    } else if ((j -= N_WP) < N_W0) {
        src = w0; hi = g_w0h; lo = g_w0l; dst = j;
    } else if ((j -= N_W0) < N_WH) {
        src = wh; hi = g_whh; lo = g_whl; dst = j;
    } else {
        j -= N_WH;
        src = wo; hi = g_woh; lo = g_wol;
        int f = j / (2 * D2_ * COUP_);
        int rem = j % (2 * D2_ * COUP_);
        int row = rem / COUP_, col = rem % COUP_;
        int rnew = (row < D2_) ? (2 * row) : (2 * (row - D2_) + 1);
        dst = f * 2 * D2_ * COUP_ + rnew * COUP_ + col;
    }
    float v = src[j];
    __nv_bfloat16 h = __float2bfloat16(v);
    hi[dst] = h;
    lo[dst] = __float2bfloat16(v - __bfloat162float(h));
}

__global__ void prep_scale_kernel(const float* __restrict__ g) {
    int f = blockIdx.x;
    int c = threadIdx.x;
    float gv = g[f * C_ + c];
    float sc = 0.2f * log1pf(expf(0.5f * gv));
    g_scale[f * C_ + c] = sc;
    __shared__ float red[C_];
    red[c] = logf(sc);
    __syncthreads();
    for (int s = C_ / 2; s > 0; s >>= 1) {
        if (c < s) red[c] += red[c + s];
        __syncthreads();
    }
    if (c == 0) g_lssum[f] = red[0];
}

__global__ void zero_ld_kernel() {
    int i = blockIdx.x * blockDim.x + threadIdx.x;
    if (i < B_) g_LD[i] = 0.0f;
}

// flow-0 input prep: XF0 = split(z0 * scale0 + off0)
__global__ void prep0_full_kernel(const float* __restrict__ z0,
                                  const float* __restrict__ off0) {
    int i = blockIdx.x * blockDim.x + threadIdx.x;
    if (i < B_ * C_) {
        int c = i & (C_ - 1);
        float v = fmaf(z0[i], g_scale[c], off0[c]);
        __nv_bfloat16 h = __float2bfloat16(v);
        g_XF0h[i] = h;
        g_XF0l[i] = __float2bfloat16(v - __bfloat162float(h));
    }
}

__global__ void finalize_ld_kernel(float* __restrict__ out) {
    int r = blockIdx.x * blockDim.x + threadIdx.x;
    if (r < B_) {
        float ls = 0.0f;
#pragma unroll
        for (int f = 0; f < F_; f++) ls += g_lssum[f];
        out[(size_t)B_ * C_ + r] = g_LD[r] + ls;
    }
}

// ---------------------------------------------------------------------------
extern "C" void kernel_launch(void* const* d_in, const int* in_sizes, int n_in,
                              void* d_out, int out_size) {
    const float* z0  = (const float*)d_in[0];
    const float* Wp  = (const float*)d_in[1];
    const float* g   = (const float*)d_in[2];
    const float* off = (const float*)d_in[3];
    const float* w0  = (const float*)d_in[4];
    const float* b0  = (const float*)d_in[5];
    const float* wh  = (const float*)d_in[6];
    const float* bh  = (const float*)d_in[7];
    const float* wo  = (const float*)d_in[8];
    const float* bo  = (const float*)d_in[9];
    float* out = (float*)d_out;

    float *X0, *X1, *scaleP;
    __nv_bfloat16 *Wph, *Wpl, *w0h, *w0l, *whh, *whl, *woh, *wol;
    __nv_bfloat16 *XF0h, *XF0l, *XF1h, *XF1l, *XAh, *XAl, *HAh, *HAl, *HBh, *HBl;
    cudaGetSymbolAddress((void**)&X0, g_X0);
    cudaGetSymbolAddress((void**)&X1, g_X1);
    cudaGetSymbolAddress((void**)&scaleP, g_scale);
    cudaGetSymbolAddress((void**)&Wph, g_Wph); cudaGetSymbolAddress((void**)&Wpl, g_Wpl);
    cudaGetSymbolAddress((void**)&w0h, g_w0h); cudaGetSymbolAddress((void**)&w0l, g_w0l);
    cudaGetSymbolAddress((void**)&whh, g_whh); cudaGetSymbolAddress((void**)&whl, g_whl);
    cudaGetSymbolAddress((void**)&woh, g_woh); cudaGetSymbolAddress((void**)&wol, g_wol);
    cudaGetSymbolAddress((void**)&XF0h, g_XF0h); cudaGetSymbolAddress((void**)&XF0l, g_XF0l);
    cudaGetSymbolAddress((void**)&XF1h, g_XF1h); cudaGetSymbolAddress((void**)&XF1l, g_XF1l);
    cudaGetSymbolAddress((void**)&XAh, g_XAh); cudaGetSymbolAddress((void**)&XAl, g_XAl);
    cudaGetSymbolAddress((void**)&HAh, g_HAh); cudaGetSymbolAddress((void**)&HAl, g_HAl);
    cudaGetSymbolAddress((void**)&HBh, g_HBh); cudaGetSymbolAddress((void**)&HBl, g_HBl);

    cudaFuncSetAttribute(mma_gemm<0>, cudaFuncAttributeMaxDynamicSharedMemorySize, SM_TOTAL);
    cudaFuncSetAttribute(mma_gemm<1>, cudaFuncAttributeMaxDynamicSharedMemorySize, SM_TOTAL);
    cudaFuncSetAttribute(mma_gemm<2>, cudaFuncAttributeMaxDynamicSharedMemorySize, SM_TOTAL);

    zero_ld_kernel<<<(B_ + 255) / 256, 256>>>();
    prep_scale_kernel<<<F_, C_>>>(g);
    split_all_kernel<<<(N_SPLIT_TOTAL + 255) / 256, 256>>>(Wp, w0, wh, wo);
    prep0_full_kernel<<<(B_ * C_ + 255) / 256, 256>>>(z0, off);

    for (int f = 0; f < F_; f++) {
        float* Xcur = (f & 1) ? X1 : X0;
        __nv_bfloat16* XFih = (f & 1) ? XF1h : XF0h;
        __nv_bfloat16* XFil = (f & 1) ? XF1l : XF0l;
        __nv_bfloat16* XFnh = (f & 1) ? XF0h : XF1h;
        __nv_bfloat16* XFnl = (f & 1) ? XF0l : XF1l;

        const __nv_bfloat16* Wph_f = Wph + (size_t)f * C_ * C_;
        const __nv_bfloat16* Wpl_f = Wpl + (size_t)f * C_ * C_;
        const __nv_bfloat16* w0h_f = w0h + (size_t)f * COUP_ * D1_;
        const __nv_bfloat16* w0l_f = w0l + (size_t)f * COUP_ * D1_;
        const __nv_bfloat16* whh0  = whh + (size_t)f * NBL_ * COUP_ * COUP_;
        const __nv_bfloat16* whl0  = whl + (size_t)f * NBL_ * COUP_ * COUP_;
        const __nv_bfloat16* whh1  = whh0 + (size_t)COUP_ * COUP_;
        const __nv_bfloat16* whl1  = whl0 + (size_t)COUP_ * COUP_;
        const __nv_bfloat16* woh_f = woh + (size_t)f * 2 * D2_ * COUP_;
        const __nv_bfloat16* wol_f = wol + (size_t)f * 2 * D2_ * COUP_;
        const float* b0_f  = b0 + (size_t)f * COUP_;
        const float* bh_f0 = bh + (size_t)f * NBL_ * COUP_;
        const float* bh_f1 = bh_f0 + COUP_;
        const float* bo_f  = bo + (size_t)f * 2 * D2_;

        int last = (f == F_ - 1) ? 1 : 0;
        const float* sc_n  = scaleP + (size_t)((f + 1) % F_) * C_;
        const float* off_n = off + (size_t)((f + 1) % F_) * C_;

        // 1) G1: X = XF @ Wp^T ; Xcur fp32 + XA splits + XFnext x1-part
        mma_gemm<0><<<dim3(C_ / 128, B_ / 128), 256, SM_TOTAL>>>(
            XFih, XFil, Wph_f, Wpl_f, nullptr,
            Xcur, C_, XAh, XAl, D1_, D1_, C_,
            sc_n, off_n, XFnh, XFnl, nullptr, out, last);

        // 2) G2: H = relu(x1 @ w0^T + b0)
        mma_gemm<1><<<dim3(COUP_ / 128, B_ / 128), 256, SM_TOTAL>>>(
            XAh, XAl, w0h_f, w0l_f, b0_f,
            nullptr, 0, HAh, HAl, COUP_, COUP_, D1_,
            nullptr, nullptr, nullptr, nullptr, nullptr, nullptr, 0);

        // 3) G3
        mma_gemm<1><<<dim3(COUP_ / 128, B_ / 128), 256, SM_TOTAL>>>(
            HAh, HAl, whh0, whl0, bh_f0,
            nullptr, 0, HBh, HBl, COUP_, COUP_, COUP_,
            nullptr, nullptr, nullptr, nullptr, nullptr, nullptr, 0);

        // 4) G4
        mma_gemm<1><<<dim3(COUP_ / 128, B_ / 128), 256, SM_TOTAL>>>(
            HBh, HBl, whh1, whl1, bh_f1,
            nullptr, 0, HAh, HAl, COUP_, COUP_, COUP_,
            nullptr, nullptr, nullptr, nullptr, nullptr, nullptr, 0);

        // 5) G5 + fused coupling (wo row-permuted so cols pair (s_j, t_j))
        mma_gemm<2><<<dim3((2 * D2_) / 128, B_ / 128), 256, SM_TOTAL>>>(
            HAh, HAl, woh_f, wol_f, bo_f,
            nullptr, 0, nullptr, nullptr, 0, 0, COUP_,
            sc_n, off_n, XFnh, XFnl, Xcur, out, last);
    }

    finalize_ld_kernel<<<(B_ + 255) / 256, 256>>>(out);
}

// round 14
// speedup vs baseline: 2.6229x; 1.2755x over previous
#include <cuda_runtime.h>
#include <cuda_bf16.h>
#include <cstdint>
#include <math.h>

// Problem constants
#define B_    8192
#define C_    512
#define F_    8
#define COUP_ 1024
#define NBL_  2
#define D1_   256
#define D2_   256

// ---------------------------------------------------------------------------
// Scratch (device globals — no allocations allowed)
// ---------------------------------------------------------------------------
__device__ float g_X0[B_ * C_];
__device__ float g_X1[B_ * C_];
__device__ float g_LD[B_];
__device__ float g_scale[F_ * C_];
__device__ float g_lssum[F_];

// x-path weights: split-bf16 (G1 stays high precision)
__device__ __nv_bfloat16 g_Wph[F_ * C_ * C_], g_Wpl[F_ * C_ * C_];
// subnet weights: tf32-rounded fp32 (wo ROW-PERMUTED: new 2j = s_j, 2j+1 = t_j)
__device__ float g_w032[F_ * COUP_ * D1_];
__device__ float g_wh32[F_ * NBL_ * COUP_ * COUP_];
__device__ float g_wo32[F_ * 2 * D2_ * COUP_];

// activations: XF split-bf16 ping-pong (x-path); subnet fp32 (tf32-rounded)
__device__ __nv_bfloat16 g_XF0h[B_ * C_], g_XF0l[B_ * C_];
__device__ __nv_bfloat16 g_XF1h[B_ * C_], g_XF1l[B_ * C_];
__device__ float g_XA32[B_ * D1_];
__device__ float g_HA32[B_ * COUP_];
__device__ float g_HB32[B_ * COUP_];

// ---------------------------------------------------------------------------
// Helpers
// ---------------------------------------------------------------------------
__device__ __forceinline__ uint32_t smem_u32(const void* p) {
    uint32_t a;
    asm("{ .reg .u64 t; cvta.to.shared.u64 t, %1; cvt.u32.u64 %0, t; }" : "=r"(a) : "l"(p));
    return a;
}
__device__ __forceinline__ void cpasync16(uint32_t s, const void* g) {
    asm volatile("cp.async.cg.shared.global [%0], [%1], 16;" :: "r"(s), "l"(g) : "memory");
}
__device__ __forceinline__ void cp_commit() { asm volatile("cp.async.commit_group;" ::: "memory"); }
__device__ __forceinline__ void cp_wait0()  { asm volatile("cp.async.wait_group 0;" ::: "memory"); }
__device__ __forceinline__ void cp_wait1()  { asm volatile("cp.async.wait_group 1;" ::: "memory"); }
__device__ __forceinline__ void ldsm4(uint32_t* r, uint32_t addr) {
    asm volatile("ldmatrix.sync.aligned.m8n8.x4.shared.b16 {%0,%1,%2,%3}, [%4];"
                 : "=r"(r[0]), "=r"(r[1]), "=r"(r[2]), "=r"(r[3]) : "r"(addr));
}
__device__ __forceinline__ void mma16816(float* d, const uint32_t* a, const uint32_t* b) {
    asm("mma.sync.aligned.m16n8k16.row.col.f32.bf16.bf16.f32 "
        "{%0,%1,%2,%3}, {%4,%5,%6,%7}, {%8,%9}, {%0,%1,%2,%3};"
        : "+f"(d[0]), "+f"(d[1]), "+f"(d[2]), "+f"(d[3])
        : "r"(a[0]), "r"(a[1]), "r"(a[2]), "r"(a[3]), "r"(b[0]), "r"(b[1]));
}
__device__ __forceinline__ void mma1688t(float* d, const uint32_t* a, const uint32_t* b) {
    asm("mma.sync.aligned.m16n8k8.row.col.f32.tf32.tf32.f32 "
        "{%0,%1,%2,%3}, {%4,%5,%6,%7}, {%8,%9}, {%0,%1,%2,%3};"
        : "+f"(d[0]), "+f"(d[1]), "+f"(d[2]), "+f"(d[3])
        : "r"(a[0]), "r"(a[1]), "r"(a[2]), "r"(a[3]), "r"(b[0]), "r"(b[1]));
}
__device__ __forceinline__ uint32_t pk2(__nv_bfloat16 a, __nv_bfloat16 b) {
    return (uint32_t)__bfloat16_as_ushort(a) | ((uint32_t)__bfloat16_as_ushort(b) << 16);
}
__device__ __forceinline__ void split_store(__nv_bfloat16* hp, __nv_bfloat16* lp,
                                            float a, float b) {
    __nv_bfloat16 ha = __float2bfloat16(a), hb = __float2bfloat16(b);
    *(uint32_t*)hp = pk2(ha, hb);
    *(uint32_t*)lp = pk2(__float2bfloat16(a - __bfloat162float(ha)),
                         __float2bfloat16(b - __bfloat162float(hb)));
}
__device__ __forceinline__ float tf32r(float x) {
    uint32_t u = __float_as_uint(x), o;
    asm("cvt.rna.tf32.f32 %0, %1;" : "=r"(o) : "r"(u));
    return __uint_as_float(o);
}

// smem: both paths use 32KB stages, 3 stages + 512B bias = 98816 -> 2 CTAs/SM
#define TILE_BYTES 8192
#define STAGE_BYTES 32768
#define SM_BIAS_OFF (3 * STAGE_BYTES)
#define SM_TOTAL (SM_BIAS_OFF + 512)

// tf32 smem addressing: 128 rows x 32 fp32 (128B/row); 16B chunk rotation (q+row)&7
__device__ __forceinline__ uint32_t taddr(int row, int kcol) {
    return (uint32_t)(row * 128 + ((((kcol >> 2) + row) & 7) << 4) + ((kcol & 3) << 2));
}

// ---------------------------------------------------------------------------
// G1: split-bf16 GEMM (x-path). X = XF @ Wp^T.
// Epilogue: Xcur fp32 (+out if last), XA32 = tf32(x1), XFnext x1 split (if !last)
// ---------------------------------------------------------------------------
__global__ __launch_bounds__(256)
void g1_gemm(const __nv_bfloat16* __restrict__ Ah, const __nv_bfloat16* __restrict__ Al,
             const __nv_bfloat16* __restrict__ Bh, const __nv_bfloat16* __restrict__ Bl,
             float* __restrict__ Yf,
             const float* __restrict__ scn, const float* __restrict__ offn,
             __nv_bfloat16* __restrict__ xfnh, __nv_bfloat16* __restrict__ xfnl,
             float* __restrict__ outp, int last) {
    extern __shared__ char smem[];
    const uint32_t sb = smem_u32(smem);
    const int tid  = threadIdx.x;
    const int lane = tid & 31;
    const int wid  = tid >> 5;
    const int warp_m = wid & 3;
    const int warp_n = wid >> 2;
    const int m0 = blockIdx.y * 128;
    const int n0 = blockIdx.x * 128;
    const int K = C_;

    float acc[2][8][4];
#pragma unroll
    for (int mt = 0; mt < 2; mt++)
#pragma unroll
        for (int nt = 0; nt < 8; nt++)
#pragma unroll
            for (int q = 0; q < 4; q++) acc[mt][nt][q] = 0.0f;

    const int nchunks = K >> 5;

    auto prefetch = [&](int st, int kb) {
        uint32_t base = sb + st * STAGE_BYTES;
#pragma unroll
        for (int i = 0; i < 2; i++) {
            int v = tid + i * 256;
            int r = v >> 2, c = v & 3;
            uint32_t sw = (uint32_t)((c ^ ((r >> 1) & 3)) << 4) + r * 64;
            size_t ga = (size_t)(m0 + r) * K + kb + c * 8;
            size_t gb = (size_t)(n0 + r) * K + kb + c * 8;
            cpasync16(base + sw,                  Ah + ga);
            cpasync16(base + TILE_BYTES + sw,     Al + ga);
            cpasync16(base + 2 * TILE_BYTES + sw, Bh + gb);
            cpasync16(base + 3 * TILE_BYTES + sw, Bl + gb);
        }
        cp_commit();
    };

    auto compute = [&](int st) {
        uint32_t base = sb + st * STAGE_BYTES;
#pragma unroll
        for (int ks = 0; ks < 2; ks++) {
            uint32_t ah[2][4], al_[2][4];
#pragma unroll
            for (int mt = 0; mt < 2; mt++) {
                int gq  = lane >> 3;
                int row = warp_m * 32 + mt * 16 + (lane & 7) + (gq & 1) * 8;
                int ch  = ks * 2 + (gq >> 1);
                uint32_t o = row * 64 + ((ch ^ ((row >> 1) & 3)) << 4);
                ldsm4(ah[mt],  base + o);
                ldsm4(al_[mt], base + TILE_BYTES + o);
            }
            uint32_t bh_[4][4], bl_[4][4];
#pragma unroll
            for (int nt = 0; nt < 4; nt++) {
                int row = warp_n * 64 + nt * 16 + (lane & 7) + ((lane >> 4) & 1) * 8;
                int ch  = ks * 2 + ((lane >> 3) & 1);
                uint32_t o = row * 64 + ((ch ^ ((row >> 1) & 3)) << 4);
                ldsm4(bh_[nt], base + 2 * TILE_BYTES + o);
                ldsm4(bl_[nt], base + 3 * TILE_BYTES + o);
            }
#pragma unroll
            for (int mt = 0; mt < 2; mt++)
#pragma unroll
                for (int nt = 0; nt < 4; nt++)
#pragma unroll
                    for (int hf = 0; hf < 2; hf++)
                        mma16816(acc[mt][nt * 2 + hf], ah[mt], &bh_[nt][hf * 2]);
#pragma unroll
            for (int mt = 0; mt < 2; mt++)
#pragma unroll
                for (int nt = 0; nt < 4; nt++)
#pragma unroll
                    for (int hf = 0; hf < 2; hf++)
                        mma16816(acc[mt][nt * 2 + hf], ah[mt], &bl_[nt][hf * 2]);
#pragma unroll
            for (int mt = 0; mt < 2; mt++)
#pragma unroll
                for (int nt = 0; nt < 4; nt++)
#pragma unroll
                    for (int hf = 0; hf < 2; hf++)
                        mma16816(acc[mt][nt * 2 + hf], al_[mt], &bh_[nt][hf * 2]);
        }
    };

    prefetch(0, 0);
    prefetch(1, 32);
    for (int kc = 0; kc < nchunks; kc++) {
        if (kc + 1 < nchunks) cp_wait1();
        else                  cp_wait0();
        __syncthreads();
        if (kc + 2 < nchunks) prefetch((kc + 2) % 3, (kc + 2) * 32);
        compute(kc % 3);
    }

    const int qr  = lane >> 2;
    const int qc2 = (lane & 3) * 2;
#pragma unroll
    for (int mt = 0; mt < 2; mt++) {
        int r0 = m0 + warp_m * 32 + mt * 16 + qr;
        int r1 = r0 + 8;
#pragma unroll
        for (int nt = 0; nt < 8; nt++) {
            float* d = acc[mt][nt];
            int col_g = n0 + warp_n * 64 + nt * 8 + qc2;
            float v00 = d[0], v01 = d[1], v10 = d[2], v11 = d[3];
            *(float2*)(Yf + (size_t)r0 * C_ + col_g) = make_float2(v00, v01);
            *(float2*)(Yf + (size_t)r1 * C_ + col_g) = make_float2(v10, v11);
            if (last) {
                *(float2*)(outp + (size_t)r0 * C_ + col_g) = make_float2(v00, v01);
                *(float2*)(outp + (size_t)r1 * C_ + col_g) = make_float2(v10, v11);
            }
            if (col_g < D1_) {
                *(float2*)(g_XA32 + (size_t)r0 * D1_ + col_g) = make_float2(tf32r(v00), tf32r(v01));
                *(float2*)(g_XA32 + (size_t)r1 * D1_ + col_g) = make_float2(tf32r(v10), tf32r(v11));
                if (!last) {
                    float u00 = fmaf(v00, scn[col_g],     offn[col_g]);
                    float u01 = fmaf(v01, scn[col_g + 1], offn[col_g + 1]);
                    float u10 = fmaf(v10, scn[col_g],     offn[col_g]);
                    float u11 = fmaf(v11, scn[col_g + 1], offn[col_g + 1]);
                    split_store(xfnh + (size_t)r0 * C_ + col_g, xfnl + (size_t)r0 * C_ + col_g, u00, u01);
                    split_store(xfnh + (size_t)r1 * C_ + col_g, xfnl + (size_t)r1 * C_ + col_g, u10, u11);
                }
            }
        }
    }
}

// ---------------------------------------------------------------------------
// tf32 GEMM: Y[M, N] = act(alpha*(A @ B^T + bias)); A,B fp32 (tf32-rounded)
// MODE 1: relu + tf32-rounded fp32 out.  MODE 2: fused coupling epilogue.
// tile 128x128x32, warp 32x64, m16n8k8 tf32.
// ---------------------------------------------------------------------------
template <int MODE>
__global__ __launch_bounds__(256)
void tf_gemm(const float* __restrict__ A, const float* __restrict__ Bp,
             const float* __restrict__ bias,
             float* __restrict__ Yf, int ldy, int K,
             const float* __restrict__ scn, const float* __restrict__ offn,
             __nv_bfloat16* __restrict__ xfnh, __nv_bfloat16* __restrict__ xfnl,
             const float* __restrict__ Xc,
             float* __restrict__ outp, int last) {
    extern __shared__ char smem[];
    const uint32_t sb = smem_u32(smem);
    const int tid  = threadIdx.x;
    const int lane = tid & 31;
    const int wid  = tid >> 5;
    const int warp_m = wid & 3;
    const int warp_n = wid >> 2;
    const int m0 = blockIdx.y * 128;
    const int n0 = blockIdx.x * 128;
    const int g  = lane >> 2;
    const int tig = lane & 3;

    float* bias_s = (float*)(smem + SM_BIAS_OFF);
    for (int j = tid; j < 128; j += 256) {
        if (MODE == 2) {
            int rn = n0 + j;
            int old = (rn & 1) ? ((rn >> 1) + 256) : (rn >> 1);
            bias_s[j] = bias[old];
        } else {
            bias_s[j] = bias[n0 + j];
        }
    }

    float acc[2][8][4];
#pragma unroll
    for (int mt = 0; mt < 2; mt++)
#pragma unroll
        for (int nt = 0; nt < 8; nt++)
#pragma unroll
            for (int q = 0; q < 4; q++) acc[mt][nt][q] = 0.0f;

    const int nchunks = K >> 5;

    auto prefetch = [&](int st, int kb) {
        uint32_t base = sb + st * STAGE_BYTES;
#pragma unroll
        for (int i = 0; i < 4; i++) {
            int v = tid + i * 256;              // 0..1023
            int r = v >> 3, q = v & 7;
            uint32_t dst = (uint32_t)(r * 128 + (((q + r) & 7) << 4));
            cpasync16(base + dst,         A  + (size_t)(m0 + r) * K + kb + q * 4);
            cpasync16(base + 16384 + dst, Bp + (size_t)(n0 + r) * K + kb + q * 4);
        }
        cp_commit();
    };

    auto compute = [&](int st) {
        uint32_t baseA = sb + st * STAGE_BYTES;
        uint32_t baseB = baseA + 16384;
#pragma unroll
        for (int ks = 0; ks < 4; ks++) {
            int k0 = ks * 8 + tig, k2 = k0 + 4;
            uint32_t a[2][4];
#pragma unroll
            for (int mt = 0; mt < 2; mt++) {
                int r = warp_m * 32 + mt * 16 + g;
                a[mt][0] = *(const uint32_t*)(smem + (baseA - sb) + taddr(r,     k0));
                a[mt][1] = *(const uint32_t*)(smem + (baseA - sb) + taddr(r + 8, k0));
                a[mt][2] = *(const uint32_t*)(smem + (baseA - sb) + taddr(r,     k2));
                a[mt][3] = *(const uint32_t*)(smem + (baseA - sb) + taddr(r + 8, k2));
            }
            uint32_t b[8][2];
#pragma unroll
            for (int nt = 0; nt < 8; nt++) {
                int r = warp_n * 64 + nt * 8 + g;
                b[nt][0] = *(const uint32_t*)(smem + (baseB - sb) + taddr(r, k0));
                b[nt][1] = *(const uint32_t*)(smem + (baseB - sb) + taddr(r, k2));
            }
#pragma unroll
            for (int mt = 0; mt < 2; mt++)
#pragma unroll
                for (int nt = 0; nt < 8; nt++)
                    mma1688t(acc[mt][nt], a[mt], b[nt]);
        }
    };

    prefetch(0, 0);
    prefetch(1, 32);
    for (int kc = 0; kc < nchunks; kc++) {
        if (kc + 1 < nchunks) cp_wait1();
        else                  cp_wait0();
        __syncthreads();
        if (kc + 2 < nchunks) prefetch((kc + 2) % 3, (kc + 2) * 32);
        compute(kc % 3);
    }

    const int qr  = lane >> 2;
    const int qc2 = (lane & 3) * 2;
#pragma unroll
    for (int mt = 0; mt < 2; mt++) {
        int r0 = m0 + warp_m * 32 + mt * 16 + qr;
        int r1 = r0 + 8;
        float sum_s0 = 0.0f, sum_s1 = 0.0f;
#pragma unroll
        for (int nt = 0; nt < 8; nt++) {
            float* d = acc[mt][nt];
            int col_l = warp_n * 64 + nt * 8 + qc2;
            int col_g = n0 + col_l;
            if (MODE == 2) {
                int jg = col_g >> 1;
                float bs = bias_s[col_l], bt = bias_s[col_l + 1];
                float s0 = 2.0f * tanhf((d[0] + bs) * 0.1f);
                float t0 = (d[1] + bt) * 0.1f;
                float s1 = 2.0f * tanhf((d[2] + bs) * 0.1f);
                float t1 = (d[3] + bt) * 0.1f;
                float nx0 = Xc[(size_t)r0 * C_ + D1_ + jg] * expf(s0) + t0;
                float nx1 = Xc[(size_t)r1 * C_ + D1_ + jg] * expf(s1) + t1;
                sum_s0 += s0;
                sum_s1 += s1;
                if (!last) {
                    float u0 = fmaf(nx0, scn[D1_ + jg], offn[D1_ + jg]);
                    float u1 = fmaf(nx1, scn[D1_ + jg], offn[D1_ + jg]);
                    __nv_bfloat16 h0 = __float2bfloat16(u0);
                    __nv_bfloat16 h1 = __float2bfloat16(u1);
                    xfnh[(size_t)r0 * C_ + D1_ + jg] = h0;
                    xfnh[(size_t)r1 * C_ + D1_ + jg] = h1;
                    xfnl[(size_t)r0 * C_ + D1_ + jg] = __float2bfloat16(u0 - __bfloat162float(h0));
                    xfnl[(size_t)r1 * C_ + D1_ + jg] = __float2bfloat16(u1 - __bfloat162float(h1));
                } else {
                    outp[(size_t)r0 * C_ + D1_ + jg] = nx0;
                    outp[(size_t)r1 * C_ + D1_ + jg] = nx1;
                }
            } else {
                float bb0 = bias_s[col_l], bb1 = bias_s[col_l + 1];
                float v00 = fmaxf(d[0] + bb0, 0.0f), v01 = fmaxf(d[1] + bb1, 0.0f);
                float v10 = fmaxf(d[2] + bb0, 0.0f), v11 = fmaxf(d[3] + bb1, 0.0f);
                *(float2*)(Yf + (size_t)r0 * ldy + col_g) = make_float2(tf32r(v00), tf32r(v01));
                *(float2*)(Yf + (size_t)r1 * ldy + col_g) = make_float2(tf32r(v10), tf32r(v11));
            }
        }
        if (MODE == 2) {
            sum_s0 += __shfl_xor_sync(0xFFFFFFFFu, sum_s0, 1);
            sum_s0 += __shfl_xor_sync(0xFFFFFFFFu, sum_s0, 2);
            sum_s1 += __shfl_xor_sync(0xFFFFFFFFu, sum_s1, 1);
            sum_s1 += __shfl_xor_sync(0xFFFFFFFFu, sum_s1, 2);
            if ((lane & 3) == 0) {
                atomicAdd(g_LD + r0, sum_s0);
                atomicAdd(g_LD + r1, sum_s1);
            }
        }
    }
}

// ---------------------------------------------------------------------------
// Prep kernels
// ---------------------------------------------------------------------------
#define N_WP (F_ * C_ * C_)
#define N_W0 (F_ * COUP_ * D1_)
#define N_WH (F_ * NBL_ * COUP_ * COUP_)
#define N_WO (F_ * 2 * D2_ * COUP_)
#define N_TF_TOTAL (N_W0 + N_WH + N_WO)

__global__ void split_wp_kernel(const float* __restrict__ Wp) {
    int i = blockIdx.x * blockDim.x + threadIdx.x;
    if (i >= N_WP) return;
    float v = Wp[i];
    __nv_bfloat16 h = __float2bfloat16(v);
    g_Wph[i] = h;
    g_Wpl[i] = __float2bfloat16(v - __bfloat162float(h));
}

__global__ void tf32_weights_kernel(const float* __restrict__ w0,
                                    const float* __restrict__ wh,
                                    const float* __restrict__ wo) {
    int i = blockIdx.x * blockDim.x + threadIdx.x;
    if (i >= N_TF_TOTAL) return;
    int j = i;
    if (j < N_W0) {
        g_w032[j] = tf32r(w0[j]);
    } else if ((j -= N_W0) < N_WH) {
        g_wh32[j] = tf32r(wh[j]);
    } else {
        j -= N_WH;
        int f = j / (2 * D2_ * COUP_);
        int rem = j % (2 * D2_ * COUP_);
        int row = rem / COUP_, col = rem % COUP_;
        int rnew = (row < D2_) ? (2 * row) : (2 * (row - D2_) + 1);
        g_wo32[f * 2 * D2_ * COUP_ + rnew * COUP_ + col] = tf32r(wo[j]);
    }
}

__global__ void prep_scale_kernel(const float* __restrict__ g) {
    int f = blockIdx.x;
    int c = threadIdx.x;
    float gv = g[f * C_ + c];
    float sc = 0.2f * log1pf(expf(0.5f * gv));
    g_scale[f * C_ + c] = sc;
    __shared__ float red[C_];
    red[c] = logf(sc);
    __syncthreads();
    for (int s = C_ / 2; s > 0; s >>= 1) {
        if (c < s) red[c] += red[c + s];
        __syncthreads();
    }
    if (c == 0) g_lssum[f] = red[0];
}

__global__ void zero_ld_kernel() {
    int i = blockIdx.x * blockDim.x + threadIdx.x;
    if (i < B_) g_LD[i] = 0.0f;
}

__global__ void prep0_full_kernel(const float* __restrict__ z0,
                                  const float* __restrict__ off0) {
    int i = blockIdx.x * blockDim.x + threadIdx.x;
    if (i < B_ * C_) {
        int c = i & (C_ - 1);
        float v = fmaf(z0[i], g_scale[c], off0[c]);
        __nv_bfloat16 h = __float2bfloat16(v);
        g_XF0h[i] = h;
        g_XF0l[i] = __float2bfloat16(v - __bfloat162float(h));
    }
}

__global__ void finalize_ld_kernel(float* __restrict__ out) {
    int r = blockIdx.x * blockDim.x + threadIdx.x;
    if (r < B_) {
        float ls = 0.0f;
#pragma unroll
        for (int f = 0; f < F_; f++) ls += g_lssum[f];
        out[(size_t)B_ * C_ + r] = g_LD[r] + ls;
    }
}

// ---------------------------------------------------------------------------
extern "C" void kernel_launch(void* const* d_in, const int* in_sizes, int n_in,
                              void* d_out, int out_size) {
    const float* z0  = (const float*)d_in[0];
    const float* Wp  = (const float*)d_in[1];
    const float* g   = (const float*)d_in[2];
    const float* off = (const float*)d_in[3];
    const float* w0  = (const float*)d_in[4];
    const float* b0  = (const float*)d_in[5];
    const float* wh  = (const float*)d_in[6];
    const float* bh  = (const float*)d_in[7];
    const float* wo  = (const float*)d_in[8];
    const float* bo  = (const float*)d_in[9];
    float* out = (float*)d_out;

    float *X0, *X1, *scaleP, *XA32, *HA32, *HB32, *w032, *wh32, *wo32;
    __nv_bfloat16 *Wph, *Wpl, *XF0h, *XF0l, *XF1h, *XF1l;
    cudaGetSymbolAddress((void**)&X0, g_X0);
    cudaGetSymbolAddress((void**)&X1, g_X1);
    cudaGetSymbolAddress((void**)&scaleP, g_scale);
    cudaGetSymbolAddress((void**)&Wph, g_Wph); cudaGetSymbolAddress((void**)&Wpl, g_Wpl);
    cudaGetSymbolAddress((void**)&w032, g_w032);
    cudaGetSymbolAddress((void**)&wh32, g_wh32);
    cudaGetSymbolAddress((void**)&wo32, g_wo32);
    cudaGetSymbolAddress((void**)&XF0h, g_XF0h); cudaGetSymbolAddress((void**)&XF0l, g_XF0l);
    cudaGetSymbolAddress((void**)&XF1h, g_XF1h); cudaGetSymbolAddress((void**)&XF1l, g_XF1l);
    cudaGetSymbolAddress((void**)&XA32, g_XA32);
    cudaGetSymbolAddress((void**)&HA32, g_HA32);
    cudaGetSymbolAddress((void**)&HB32, g_HB32);

    cudaFuncSetAttribute(g1_gemm,    cudaFuncAttributeMaxDynamicSharedMemorySize, SM_TOTAL);
    cudaFuncSetAttribute(tf_gemm<1>, cudaFuncAttributeMaxDynamicSharedMemorySize, SM_TOTAL);
    cudaFuncSetAttribute(tf_gemm<2>, cudaFuncAttributeMaxDynamicSharedMemorySize, SM_TOTAL);

    zero_ld_kernel<<<(B_ + 255) / 256, 256>>>();
    prep_scale_kernel<<<F_, C_>>>(g);
    split_wp_kernel<<<(N_WP + 255) / 256, 256>>>(Wp);
    tf32_weights_kernel<<<(N_TF_TOTAL + 255) / 256, 256>>>(w0, wh, wo);
    prep0_full_kernel<<<(B_ * C_ + 255) / 256, 256>>>(z0, off);

    for (int f = 0; f < F_; f++) {
        float* Xcur = (f & 1) ? X1 : X0;
        __nv_bfloat16* XFih = (f & 1) ? XF1h : XF0h;
        __nv_bfloat16* XFil = (f & 1) ? XF1l : XF0l;
        __nv_bfloat16* XFnh = (f & 1) ? XF0h : XF1h;
        __nv_bfloat16* XFnl = (f & 1) ? XF0l : XF1l;

        const __nv_bfloat16* Wph_f = Wph + (size_t)f * C_ * C_;
        const __nv_bfloat16* Wpl_f = Wpl + (size_t)f * C_ * C_;
        const float* w0_f  = w032 + (size_t)f * COUP_ * D1_;
        const float* wh_f0 = wh32 + (size_t)f * NBL_ * COUP_ * COUP_;
        const float* wh_f1 = wh_f0 + (size_t)COUP_ * COUP_;
        const float* wo_f  = wo32 + (size_t)f * 2 * D2_ * COUP_;
        const float* b0_f  = b0 + (size_t)f * COUP_;
        const float* bh_f0 = bh + (size_t)f * NBL_ * COUP_;
        const float* bh_f1 = bh_f0 + COUP_;
        const float* bo_f  = bo + (size_t)f * 2 * D2_;

        int last = (f == F_ - 1) ? 1 : 0;
        const float* sc_n  = scaleP + (size_t)((f + 1) % F_) * C_;
        const float* off_n = off + (size_t)((f + 1) % F_) * C_;

        // 1) G1 (split-bf16): X = XF @ Wp^T
        g1_gemm<<<dim3(C_ / 128, B_ / 128), 256, SM_TOTAL>>>(
            XFih, XFil, Wph_f, Wpl_f, Xcur,
            sc_n, off_n, XFnh, XFnl, out, last);

        // 2) G2 (tf32): HA = relu(x1 @ w0^T + b0), K=256
        tf_gemm<1><<<dim3(COUP_ / 128, B_ / 128), 256, SM_TOTAL>>>(
            XA32, w0_f, b0_f, HA32, COUP_, D1_,
            nullptr, nullptr, nullptr, nullptr, nullptr, nullptr, 0);

        // 3) G3 (tf32): HB = relu(HA @ wh0^T + bh0), K=1024
        tf_gemm<1><<<dim3(COUP_ / 128, B_ / 128), 256, SM_TOTAL>>>(
            HA32, wh_f0, bh_f0, HB32, COUP_, COUP_,
            nullptr, nullptr, nullptr, nullptr, nullptr, nullptr, 0);

        // 4) G4 (tf32): HA = relu(HB @ wh1^T + bh1), K=1024
        tf_gemm<1><<<dim3(COUP_ / 128, B_ / 128), 256, SM_TOTAL>>>(
            HB32, wh_f1, bh_f1, HA32, COUP_, COUP_,
            nullptr, nullptr, nullptr, nullptr, nullptr, nullptr, 0);

        // 5) G5 (tf32) + fused coupling (wo row-permuted: cols pair (s_j, t_j))
        tf_gemm<2><<<dim3((2 * D2_) / 128, B_ / 128), 256, SM_TOTAL>>>(
            HA32, wo_f, bo_f, nullptr, 0, COUP_,
            sc_n, off_n, XFnh, XFnl, Xcur, out, last);
    }

    finalize_ld_kernel<<<(B_ + 255) / 256, 256>>>(out);
}